// round 6
// baseline (speedup 1.0000x reference)
#include <cuda_runtime.h>
#include <cuda_bf16.h>
#include <math.h>

// Problem constants
#define B_      4
#define T_      2048
#define KDIM    1024
#define HEADS   16
#define HDIM    64
#define ROWS    (B_ * T_)          // 8192
#define HALF    (KDIM / 2)         // 512

// ---------------------------------------------------------------------------
// Scratch (device globals: allocation-free per harness rules)
// ---------------------------------------------------------------------------
__device__ float g_q[ROWS * KDIM];
__device__ float g_k[ROWS * KDIM];
__device__ float g_v[ROWS * KDIM];
__device__ float g_a[ROWS * KDIM];

// ---------------------------------------------------------------------------
// Helpers
// ---------------------------------------------------------------------------
__device__ __forceinline__ unsigned f2tf(float f) {
    unsigned u;
    asm("cvt.rna.tf32.f32 %0, %1;" : "=r"(u) : "f"(f));
    return u;
}
__device__ __forceinline__ float f2tff(float f) {
    return __uint_as_float(f2tf(f));
}

// mma.sync m16n8k8 tf32: D = A*B + D
// A frag: a0=(g,t) a1=(g+8,t) a2=(g,t+4) a3=(g+8,t+4)  [g=lane>>2, t=lane&3]
// B frag: b0=(k=t,n=g) b1=(k=t+4,n=g)
// C frag: c0=(g,2t) c1=(g,2t+1) c2=(g+8,2t) c3=(g+8,2t+1)
__device__ __forceinline__ void mma_tf32(float* c, const unsigned* a, const unsigned* b) {
    asm volatile(
        "mma.sync.aligned.m16n8k8.row.col.f32.tf32.tf32.f32 "
        "{%0,%1,%2,%3}, {%4,%5,%6,%7}, {%8,%9}, {%0,%1,%2,%3};\n"
        : "+f"(c[0]), "+f"(c[1]), "+f"(c[2]), "+f"(c[3])
        : "r"(a[0]), "r"(a[1]), "r"(a[2]), "r"(a[3]), "r"(b[0]), "r"(b[1]));
}

__device__ __forceinline__ void cp16(float* dst_smem, const float* src) {
    unsigned d = (unsigned)__cvta_generic_to_shared(dst_smem);
    asm volatile("cp.async.cg.shared.global [%0], [%1], 16;\n" :: "r"(d), "l"(src));
}
#define CP_COMMIT() asm volatile("cp.async.commit_group;\n" ::: "memory")
#define CP_WAIT0()  asm volatile("cp.async.wait_group 0;\n" ::: "memory")

// in-place tf32 conversion of a 16-float smem span (4x float4)
__device__ __forceinline__ void cvt16_inplace(float* p) {
#pragma unroll
    for (int i = 0; i < 4; i++) {
        float4 v = *(float4*)(p + 4 * i);
        v.x = f2tff(v.x); v.y = f2tff(v.y);
        v.z = f2tff(v.z); v.w = f2tff(v.w);
        *(float4*)(p + 4 * i) = v;
    }
}

// ---------------------------------------------------------------------------
// Tensor-core GEMM: C[m][n] = sum_k A[m][k]*B[n][k]   (C = A @ B^T)
// MODE: 0 = plain, 1 = RoPE epilogue (Q/K proj), 2 = +bias (output proj)
// 128x128x32 CTA tile, 128 threads = 4 warps (2m x 2n), warp tile 64x64.
// cp.async 2-stage pipeline; raw fp32 lands in smem, converted to tf32 in
// place once per chunk -> mma loops pure LDS + MMA.
// Stride 36 (mod 32 = 4) -> fragment lanes hit banks 4g+t: conflict-free.
// ---------------------------------------------------------------------------
#define GS 36

template<int MODE>
__global__ __launch_bounds__(128, 2) void gemm_tc(
    const float* __restrict__ A, const float* __restrict__ B,
    const float* __restrict__ bias, float* __restrict__ C,
    int M, int N, int Kd)
{
    extern __shared__ float sm[];
    float* As = sm;                 // [2][128*GS]
    float* Bs = sm + 2 * 128 * GS;  // [2][128*GS]

    const int tid  = threadIdx.x;
    const int lane = tid & 31;
    const int warp = tid >> 5;     // 0..3
    const int g = lane >> 2;
    const int t = lane & 3;
    const int wm = warp >> 1;      // 0..1
    const int wn = warp & 1;       // 0..1
    const int bm = blockIdx.y * 128;
    const int bn = blockIdx.x * 128;

    float c[4][8][4];
#pragma unroll
    for (int i = 0; i < 4; i++)
#pragma unroll
        for (int j = 0; j < 8; j++)
#pragma unroll
            for (int e = 0; e < 4; e++) c[i][j][e] = 0.0f;

    // loader: each thread owns one full row (32 floats per chunk)
    const float* Ap = A + (size_t)(bm + tid) * Kd;
    const float* Bp = B + (size_t)(bn + tid) * Kd;
    float* Asl = &As[tid * GS];
    float* Bsl = &Bs[tid * GS];

    // prologue: stage 0 <- k0=0
#pragma unroll
    for (int i = 0; i < 8; i++) {
        cp16(Asl + 4 * i, Ap + 4 * i);
        cp16(Bsl + 4 * i, Bp + 4 * i);
    }
    CP_COMMIT();

    const int a_base0 = (wm * 64 + g) * GS;
    const int b_base0 = (wn * 64 + g) * GS;

    for (int k0 = 0; k0 < Kd; k0 += 32) {
        const int st = (k0 >> 5) & 1;
        CP_WAIT0();
        __syncthreads();
        if (k0 + 32 < Kd) {
            const int stn = st ^ 1;
            float* Asd = Asl + stn * 128 * GS;
            float* Bsd = Bsl + stn * 128 * GS;
#pragma unroll
            for (int i = 0; i < 8; i++) {
                cp16(Asd + 4 * i, Ap + k0 + 32 + 4 * i);
                cp16(Bsd + 4 * i, Bp + k0 + 32 + 4 * i);
            }
        }
        CP_COMMIT();

        // convert current stage to tf32 in place
        cvt16_inplace(Asl + st * 128 * GS);
        cvt16_inplace(Asl + st * 128 * GS + 16);
        cvt16_inplace(Bsl + st * 128 * GS);
        cvt16_inplace(Bsl + st * 128 * GS + 16);
        __syncthreads();

        const float* Ac = As + st * 128 * GS;
        const float* Bc = Bs + st * 128 * GS;
#pragma unroll
        for (int s = 0; s < 4; s++) {
            const int kc = 8 * s + t;
            unsigned a[4][4], b[8][2];
#pragma unroll
            for (int mt = 0; mt < 4; mt++) {
                const float* p = &Ac[a_base0 + mt * 16 * GS + kc];
                a[mt][0] = __float_as_uint(p[0]);
                a[mt][1] = __float_as_uint(p[8 * GS]);
                a[mt][2] = __float_as_uint(p[4]);
                a[mt][3] = __float_as_uint(p[8 * GS + 4]);
            }
#pragma unroll
            for (int nt = 0; nt < 8; nt++) {
                const float* p = &Bc[b_base0 + nt * 8 * GS + kc];
                b[nt][0] = __float_as_uint(p[0]);
                b[nt][1] = __float_as_uint(p[4]);
            }
#pragma unroll
            for (int mt = 0; mt < 4; mt++)
#pragma unroll
                for (int nt = 0; nt < 8; nt++)
                    mma_tf32(c[mt][nt], a[mt], b[nt]);
        }
    }

    // Epilogue
#pragma unroll
    for (int mt = 0; mt < 4; mt++) {
        int row = bm + wm * 64 + mt * 16 + g;
#pragma unroll
        for (int nt = 0; nt < 8; nt++) {
            int col = bn + wn * 64 + nt * 8 + 2 * t;   // even
            float v0x = c[mt][nt][0], v0y = c[mt][nt][1];
            float v1x = c[mt][nt][2], v1y = c[mt][nt][3];
            if (MODE == 1) {
                int j = col >> 1;
                float theta = powf(10000.0f, -(float)j * (1.0f / (float)HALF));
                int t0 = row & (T_ - 1);
                float s0, c0; sincosf((float)t0 * theta, &s0, &c0);
                float s1, c1; sincosf((float)(t0 + 8) * theta, &s1, &c1);
                float r0x = v0x * c0 - v0y * s0;
                float r0y = v0x * s0 + v0y * c0;
                float r1x = v1x * c1 - v1y * s1;
                float r1y = v1x * s1 + v1y * c1;
                v0x = r0x; v0y = r0y; v1x = r1x; v1y = r1y;
            } else if (MODE == 2) {
                float bx = bias[col], by = bias[col + 1];
                v0x += bx; v0y += by; v1x += bx; v1y += by;
            }
            *(float2*)&C[(size_t)row * N + col] = make_float2(v0x, v0y);
            *(float2*)&C[(size_t)(row + 8) * N + col] = make_float2(v1x, v1y);
        }
    }
}

// ---------------------------------------------------------------------------
// Flash attention, tf32 mma.  CTA = 128 q-rows x (batch*head), 4 warps.
// Warp w owns q-rows [w*32, w*32+32) = TWO 16-row m-tiles sharing all K/V
// fragment loads (halves smem bytes per q-row vs 16-row warp tiles).
// Q tf32 in smem (stride 68), K stride 68, V stride 72 (all conflict-free).
// cp.async 2-stage pipeline, in-place tf32 conversion per tile.
// P redistributed C-frag -> A-frag via shfl (no smem round-trip).
// ---------------------------------------------------------------------------
#define QSTR 68
#define KSTR 68
#define VSTR 72
#define QSZ  (128 * QSTR)              // 8704 floats
#define SSZ  (64 * KSTR + 64 * VSTR)   // 8960 floats per stage

__global__ __launch_bounds__(128, 2) void attn_tc(
    const float* __restrict__ Q, const float* __restrict__ K,
    const float* __restrict__ V, float* __restrict__ O)
{
    extern __shared__ float sm[];
    float* Qs = sm;
    float* K0 = sm + QSZ;
    float* V0 = K0 + 64 * KSTR;
    float* K1 = sm + QSZ + SSZ;
    float* V1 = K1 + 64 * KSTR;

    const int tid  = threadIdx.x;
    const int lane = tid & 31;
    const int warp = tid >> 5;          // 0..3
    const int g = lane >> 2;
    const int t = lane & 3;
    const int wrow = warp * 32;

    const int qtile = blockIdx.x;       // 0..15
    const int bh = blockIdx.y;          // 0..63
    const int b = bh >> 4;
    const int h = bh & 15;
    const size_t rowbase = (size_t)b * T_;
    const int colbase = h * HDIM;

    // K/V loader: 2 threads per row, 32 floats each
    const int lrow = tid >> 1;          // 0..63
    const int lcb  = (tid & 1) * 32;    // 0 or 32

    // ---- Stage Q tile [128 x 64]: one row per thread, cvt in place
    {
        const float* src = Q + (rowbase + qtile * 128 + tid) * KDIM + colbase;
        float* dst = Qs + tid * QSTR;
#pragma unroll
        for (int i = 0; i < 16; i++) cp16(dst + 4 * i, src + 4 * i);
        CP_COMMIT();
        CP_WAIT0();
        __syncthreads();
        cvt16_inplace(dst);
        cvt16_inplace(dst + 16);
        cvt16_inplace(dst + 32);
        cvt16_inplace(dst + 48);
        __syncthreads();
    }

    // ---- prologue: tile 0 -> stage 0
    {
        const size_t gb = (rowbase + lrow) * KDIM + colbase + lcb;
        float* kd = K0 + lrow * KSTR + lcb;
        float* vd = V0 + lrow * VSTR + lcb;
#pragma unroll
        for (int i = 0; i < 8; i++) {
            cp16(kd + 4 * i, K + gb + 4 * i);
            cp16(vd + 4 * i, V + gb + 4 * i);
        }
        CP_COMMIT();
    }

    float mrow[2][2], lrow_s[2][2];
#pragma unroll
    for (int mt = 0; mt < 2; mt++) {
        mrow[mt][0] = -1e30f; mrow[mt][1] = -1e30f;
        lrow_s[mt][0] = 0.0f; lrow_s[mt][1] = 0.0f;
    }
    float o2[2][8][4];
#pragma unroll
    for (int mt = 0; mt < 2; mt++)
#pragma unroll
        for (int j = 0; j < 8; j++)
#pragma unroll
            for (int e = 0; e < 4; e++) o2[mt][j][e] = 0.0f;

    const int s0lane = 4 * g + (t >> 1);
    const int s1lane = s0lane + 2;
    const bool odd = (t & 1);

    for (int kt = 0; kt < T_ / 64; kt++) {
        const int st = kt & 1;
        float* Kc = st ? K1 : K0;
        float* Vc = st ? V1 : V0;

        CP_WAIT0();
        __syncthreads();   // tile arrived; prev iter's smem reads done

        if (kt + 1 < T_ / 64) {
            const size_t gb = (rowbase + (kt + 1) * 64 + lrow) * KDIM + colbase + lcb;
            float* kd = (st ? K0 : K1) + lrow * KSTR + lcb;
            float* vd = (st ? V0 : V1) + lrow * VSTR + lcb;
#pragma unroll
            for (int i = 0; i < 8; i++) {
                cp16(kd + 4 * i, K + gb + 4 * i);
                cp16(vd + 4 * i, V + gb + 4 * i);
            }
        }
        CP_COMMIT();

        // convert current K/V tile to tf32 in place
        cvt16_inplace(Kc + lrow * KSTR + lcb);
        cvt16_inplace(Kc + lrow * KSTR + lcb + 16);
        cvt16_inplace(Vc + lrow * VSTR + lcb);
        cvt16_inplace(Vc + lrow * VSTR + lcb + 16);
        __syncthreads();

        // ---- S = Q K^T (warp tile 32 x 64; K frags shared by both m-tiles)
        float sc[2][8][4];
#pragma unroll
        for (int mt = 0; mt < 2; mt++)
#pragma unroll
            for (int j = 0; j < 8; j++)
#pragma unroll
                for (int e = 0; e < 4; e++) sc[mt][j][e] = 0.0f;

#pragma unroll
        for (int s = 0; s < 8; s++) {
            unsigned qa[2][4];
#pragma unroll
            for (int mt = 0; mt < 2; mt++) {
                const float* qp = &Qs[(wrow + mt * 16 + g) * QSTR + 8 * s + t];
                qa[mt][0] = __float_as_uint(qp[0]);
                qa[mt][1] = __float_as_uint(qp[8 * QSTR]);
                qa[mt][2] = __float_as_uint(qp[4]);
                qa[mt][3] = __float_as_uint(qp[8 * QSTR + 4]);
            }
#pragma unroll
            for (int j = 0; j < 8; j++) {
                const float* kb = &Kc[(j * 8 + g) * KSTR + 8 * s + t];
                unsigned bb[2] = { __float_as_uint(kb[0]), __float_as_uint(kb[4]) };
                mma_tf32(sc[0][j], qa[0], bb);
                mma_tf32(sc[1][j], qa[1], bb);
            }
        }
#pragma unroll
        for (int mt = 0; mt < 2; mt++)
#pragma unroll
            for (int j = 0; j < 8; j++)
#pragma unroll
                for (int e = 0; e < 4; e++) sc[mt][j][e] *= 0.125f;  // 1/sqrt(64)

        // ---- Online softmax per m-tile (rows g, g+8)
#pragma unroll
        for (int mt = 0; mt < 2; mt++) {
            float mx0 = -1e30f, mx1 = -1e30f;
#pragma unroll
            for (int j = 0; j < 8; j++) {
                mx0 = fmaxf(mx0, fmaxf(sc[mt][j][0], sc[mt][j][1]));
                mx1 = fmaxf(mx1, fmaxf(sc[mt][j][2], sc[mt][j][3]));
            }
            mx0 = fmaxf(mx0, __shfl_xor_sync(0xffffffffu, mx0, 1));
            mx0 = fmaxf(mx0, __shfl_xor_sync(0xffffffffu, mx0, 2));
            mx1 = fmaxf(mx1, __shfl_xor_sync(0xffffffffu, mx1, 1));
            mx1 = fmaxf(mx1, __shfl_xor_sync(0xffffffffu, mx1, 2));

            float mn0 = fmaxf(mrow[mt][0], mx0);
            float mn1 = fmaxf(mrow[mt][1], mx1);
            float corr0 = __expf(mrow[mt][0] - mn0);
            float corr1 = __expf(mrow[mt][1] - mn1);

            float rs0 = 0.0f, rs1 = 0.0f;
#pragma unroll
            for (int j = 0; j < 8; j++) {
                float p0 = f2tff(__expf(sc[mt][j][0] - mn0));
                float p1 = f2tff(__expf(sc[mt][j][1] - mn0));
                float p2 = f2tff(__expf(sc[mt][j][2] - mn1));
                float p3 = f2tff(__expf(sc[mt][j][3] - mn1));
                rs0 += p0 + p1;
                rs1 += p2 + p3;
                sc[mt][j][0] = p0; sc[mt][j][1] = p1;
                sc[mt][j][2] = p2; sc[mt][j][3] = p3;
            }
            rs0 += __shfl_xor_sync(0xffffffffu, rs0, 1);
            rs0 += __shfl_xor_sync(0xffffffffu, rs0, 2);
            rs1 += __shfl_xor_sync(0xffffffffu, rs1, 1);
            rs1 += __shfl_xor_sync(0xffffffffu, rs1, 2);

            lrow_s[mt][0] = lrow_s[mt][0] * corr0 + rs0;
            lrow_s[mt][1] = lrow_s[mt][1] * corr1 + rs1;
#pragma unroll
            for (int j = 0; j < 8; j++) {
                o2[mt][j][0] *= corr0; o2[mt][j][1] *= corr0;
                o2[mt][j][2] *= corr1; o2[mt][j][3] *= corr1;
            }
            mrow[mt][0] = mn0; mrow[mt][1] = mn1;
        }

        // ---- O += P V : V frags shared by both m-tiles
#pragma unroll
        for (int kk = 0; kk < 8; kk++) {
            unsigned pf[2][4];
#pragma unroll
            for (int mt = 0; mt < 2; mt++) {
                float v00 = __shfl_sync(0xffffffffu, sc[mt][kk][0], s0lane);
                float v01 = __shfl_sync(0xffffffffu, sc[mt][kk][1], s0lane);
                float v02 = __shfl_sync(0xffffffffu, sc[mt][kk][2], s0lane);
                float v03 = __shfl_sync(0xffffffffu, sc[mt][kk][3], s0lane);
                float v10 = __shfl_sync(0xffffffffu, sc[mt][kk][0], s1lane);
                float v11 = __shfl_sync(0xffffffffu, sc[mt][kk][1], s1lane);
                float v12 = __shfl_sync(0xffffffffu, sc[mt][kk][2], s1lane);
                float v13 = __shfl_sync(0xffffffffu, sc[mt][kk][3], s1lane);
                pf[mt][0] = __float_as_uint(odd ? v01 : v00);   // P[g   ][t]
                pf[mt][1] = __float_as_uint(odd ? v03 : v02);   // P[g+8 ][t]
                pf[mt][2] = __float_as_uint(odd ? v11 : v10);   // P[g   ][t+4]
                pf[mt][3] = __float_as_uint(odd ? v13 : v12);   // P[g+8 ][t+4]
            }
#pragma unroll
            for (int j2 = 0; j2 < 8; j2++) {
                const float* vb = &Vc[(kk * 8 + t) * VSTR + j2 * 8 + g];
                unsigned bb[2] = { __float_as_uint(vb[0]), __float_as_uint(vb[4 * VSTR]) };
                mma_tf32(o2[0][j2], pf[0], bb);
                mma_tf32(o2[1][j2], pf[1], bb);
            }
        }
    }

    // ---- Normalize and write out ([b*t][h*64])
#pragma unroll
    for (int mt = 0; mt < 2; mt++) {
        float inv0 = 1.0f / lrow_s[mt][0];
        float inv1 = 1.0f / lrow_s[mt][1];
        size_t orow0 = (rowbase + qtile * 128 + wrow + mt * 16 + g) * KDIM + colbase;
        size_t orow1 = orow0 + (size_t)8 * KDIM;
#pragma unroll
        for (int j = 0; j < 8; j++) {
            int col = 8 * j + 2 * t;
            *(float2*)&O[orow0 + col] = make_float2(o2[mt][j][0] * inv0, o2[mt][j][1] * inv0);
            *(float2*)&O[orow1 + col] = make_float2(o2[mt][j][2] * inv1, o2[mt][j][3] * inv1);
        }
    }
}

// ---------------------------------------------------------------------------
// Launcher
// ---------------------------------------------------------------------------
extern "C" void kernel_launch(void* const* d_in, const int* in_sizes, int n_in,
                              void* d_out, int out_size)
{
    const float* x  = (const float*)d_in[0];
    const float* Wq = (const float*)d_in[1];
    const float* Wk = (const float*)d_in[2];
    const float* Wv = (const float*)d_in[3];
    const float* Wu = (const float*)d_in[4];
    const float* bu = (const float*)d_in[5];
    float* out = (float*)d_out;

    float *q, *k, *v, *a;
    cudaGetSymbolAddress((void**)&q, g_q);
    cudaGetSymbolAddress((void**)&k, g_k);
    cudaGetSymbolAddress((void**)&v, g_v);
    cudaGetSymbolAddress((void**)&a, g_a);

    const int gemm_smem = 4 * 128 * GS * (int)sizeof(float);   // 73728 B
    cudaFuncSetAttribute(gemm_tc<0>, cudaFuncAttributeMaxDynamicSharedMemorySize, gemm_smem);
    cudaFuncSetAttribute(gemm_tc<1>, cudaFuncAttributeMaxDynamicSharedMemorySize, gemm_smem);
    cudaFuncSetAttribute(gemm_tc<2>, cudaFuncAttributeMaxDynamicSharedMemorySize, gemm_smem);

    dim3 ggrid(KDIM / 128, ROWS / 128);  // (8, 64)

    // QKV projections; RoPE fused into Q/K epilogues
    gemm_tc<1><<<ggrid, 128, gemm_smem>>>(x, Wq, nullptr, q, ROWS, KDIM, KDIM);
    gemm_tc<1><<<ggrid, 128, gemm_smem>>>(x, Wk, nullptr, k, ROWS, KDIM, KDIM);
    gemm_tc<0><<<ggrid, 128, gemm_smem>>>(x, Wv, nullptr, v, ROWS, KDIM, KDIM);

    // Attention: 128 q-rows per CTA, 4 warps (32 rows each)
    const int attn_smem = (QSZ + 2 * SSZ) * (int)sizeof(float);  // 106496 B
    cudaFuncSetAttribute(attn_tc, cudaFuncAttributeMaxDynamicSharedMemorySize, attn_smem);
    attn_tc<<<dim3(T_ / 128, B_ * HEADS), 128, attn_smem>>>(q, k, v, a);

    // Output projection + bias
    gemm_tc<2><<<ggrid, 128, gemm_smem>>>(a, Wu, bu, out, ROWS, KDIM, KDIM);
}

// round 7
// speedup vs baseline: 1.2805x; 1.2805x over previous
#include <cuda_runtime.h>
#include <cuda_bf16.h>
#include <math.h>

// Problem constants
#define B_      4
#define T_      2048
#define KDIM    1024
#define HEADS   16
#define HDIM    64
#define ROWS    (B_ * T_)          // 8192
#define HALF    (KDIM / 2)         // 512

// ---------------------------------------------------------------------------
// Scratch (device globals: allocation-free per harness rules)
// ---------------------------------------------------------------------------
__device__ float g_q[ROWS * KDIM];
__device__ float g_k[ROWS * KDIM];
__device__ float g_v[ROWS * KDIM];
__device__ float g_a[ROWS * KDIM];
__device__ float g_xt[ROWS * KDIM];     // tf32-rounded x
__device__ float g_wq[KDIM * KDIM];     // tf32-rounded weights
__device__ float g_wk[KDIM * KDIM];
__device__ float g_wv[KDIM * KDIM];
__device__ float g_wu[KDIM * KDIM];

// ---------------------------------------------------------------------------
// Helpers
// ---------------------------------------------------------------------------
__device__ __forceinline__ unsigned f2tf(float f) {
    unsigned u;
    asm("cvt.rna.tf32.f32 %0, %1;" : "=r"(u) : "f"(f));
    return u;
}
__device__ __forceinline__ float f2tff(float f) {
    return __uint_as_float(f2tf(f));
}

// mma.sync m16n8k8 tf32: D = A*B + D
// A frag: a0=(g,t) a1=(g+8,t) a2=(g,t+4) a3=(g+8,t+4)  [g=lane>>2, t=lane&3]
// B frag: b0=(k=t,n=g) b1=(k=t+4,n=g)
// C frag: c0=(g,2t) c1=(g,2t+1) c2=(g+8,2t) c3=(g+8,2t+1)
__device__ __forceinline__ void mma_tf32(float* c, const unsigned* a, const unsigned* b) {
    asm volatile(
        "mma.sync.aligned.m16n8k8.row.col.f32.tf32.tf32.f32 "
        "{%0,%1,%2,%3}, {%4,%5,%6,%7}, {%8,%9}, {%0,%1,%2,%3};\n"
        : "+f"(c[0]), "+f"(c[1]), "+f"(c[2]), "+f"(c[3])
        : "r"(a[0]), "r"(a[1]), "r"(a[2]), "r"(a[3]), "r"(b[0]), "r"(b[1]));
}

__device__ __forceinline__ void cp16(float* dst_smem, const float* src) {
    unsigned d = (unsigned)__cvta_generic_to_shared(dst_smem);
    asm volatile("cp.async.cg.shared.global [%0], [%1], 16;\n" :: "r"(d), "l"(src));
}
#define CP_COMMIT() asm volatile("cp.async.commit_group;\n" ::: "memory")
#define CP_WAIT0()  asm volatile("cp.async.wait_group 0;\n" ::: "memory")

// ---------------------------------------------------------------------------
// Pre-pass: RNA-round fp32 tensors to exact-tf32 values (producer-side
// rounding; all downstream mma truncation is then lossless).
// ---------------------------------------------------------------------------
__global__ void round_tf32_kernel(const float4* __restrict__ in,
                                  float4* __restrict__ out, int n4)
{
    int i = blockIdx.x * blockDim.x + threadIdx.x;
    if (i >= n4) return;
    float4 v = in[i];
    v.x = f2tff(v.x); v.y = f2tff(v.y);
    v.z = f2tff(v.z); v.w = f2tff(v.w);
    out[i] = v;
}

// ---------------------------------------------------------------------------
// Tensor-core GEMM: C[m][n] = sum_k A[m][k]*B[n][k]   (C = A @ B^T)
// Inputs MUST be exact-tf32 fp32 (pre-rounded).  No cvt anywhere.
// MODE: 0 = round-store (V proj), 1 = RoPE + round-store (Q/K proj),
//       2 = +bias, full fp32 store (final output).
// 128x128x32 CTA tile, 256 threads = 8 warps (2m x 4n), warp tile 64x32.
// cp.async 2-stage pipeline.  Stride 36 -> fragment banks 4g+t conflict-free.
// ---------------------------------------------------------------------------
#define GS 36

template<int MODE>
__global__ __launch_bounds__(256, 2) void gemm_tc(
    const float* __restrict__ A, const float* __restrict__ B,
    const float* __restrict__ bias, float* __restrict__ C,
    int M, int N, int Kd)
{
    extern __shared__ float sm[];
    float* As = sm;                 // [2][128*GS]
    float* Bs = sm + 2 * 128 * GS;  // [2][128*GS]

    const int tid  = threadIdx.x;
    const int lane = tid & 31;
    const int warp = tid >> 5;
    const int g = lane >> 2;
    const int t = lane & 3;
    const int wm = warp >> 2;      // 0..1
    const int wn = warp & 3;       // 0..3
    const int bm = blockIdx.y * 128;
    const int bn = blockIdx.x * 128;

    float c[4][4][4];
#pragma unroll
    for (int i = 0; i < 4; i++)
#pragma unroll
        for (int j = 0; j < 4; j++)
#pragma unroll
            for (int e = 0; e < 4; e++) c[i][j][e] = 0.0f;

    const int lrow = tid >> 1;          // 0..127
    const int lcb  = (tid & 1) * 16;    // 0 or 16
    const float* Ap = A + (size_t)(bm + lrow) * Kd + lcb;
    const float* Bp = B + (size_t)(bn + lrow) * Kd + lcb;
    float* Asl = &As[lrow * GS + lcb];
    float* Bsl = &Bs[lrow * GS + lcb];

    // prologue: stage 0 <- k0=0
#pragma unroll
    for (int i = 0; i < 4; i++) {
        cp16(Asl + 4 * i, Ap + 4 * i);
        cp16(Bsl + 4 * i, Bp + 4 * i);
    }
    CP_COMMIT();

    const int a_base0 = (wm * 64 + g) * GS;
    const int b_base0 = (wn * 32 + g) * GS;

    for (int k0 = 0; k0 < Kd; k0 += 32) {
        const int st = (k0 >> 5) & 1;
        CP_WAIT0();
        __syncthreads();
        if (k0 + 32 < Kd) {
            const int stn = st ^ 1;
            float* Asd = Asl + stn * 128 * GS;
            float* Bsd = Bsl + stn * 128 * GS;
#pragma unroll
            for (int i = 0; i < 4; i++) {
                cp16(Asd + 4 * i, Ap + k0 + 32 + 4 * i);
                cp16(Bsd + 4 * i, Bp + k0 + 32 + 4 * i);
            }
        }
        CP_COMMIT();

        const float* Ac = As + st * 128 * GS;
        const float* Bc = Bs + st * 128 * GS;
#pragma unroll
        for (int s = 0; s < 4; s++) {
            unsigned a[4][4], b[4][2];
            const int kc = 8 * s + t;
#pragma unroll
            for (int mt = 0; mt < 4; mt++) {
                const float* p = &Ac[a_base0 + mt * 16 * GS + kc];
                a[mt][0] = __float_as_uint(p[0]);
                a[mt][1] = __float_as_uint(p[8 * GS]);
                a[mt][2] = __float_as_uint(p[4]);
                a[mt][3] = __float_as_uint(p[8 * GS + 4]);
            }
#pragma unroll
            for (int nt = 0; nt < 4; nt++) {
                const float* p = &Bc[b_base0 + nt * 8 * GS + kc];
                b[nt][0] = __float_as_uint(p[0]);
                b[nt][1] = __float_as_uint(p[4]);
            }
#pragma unroll
            for (int mt = 0; mt < 4; mt++)
#pragma unroll
                for (int nt = 0; nt < 4; nt++)
                    mma_tf32(c[mt][nt], a[mt], b[nt]);
        }
    }

    // Epilogue
#pragma unroll
    for (int mt = 0; mt < 4; mt++) {
        int row = bm + wm * 64 + mt * 16 + g;
#pragma unroll
        for (int nt = 0; nt < 4; nt++) {
            int col = bn + wn * 32 + nt * 8 + 2 * t;   // even
            float v0x = c[mt][nt][0], v0y = c[mt][nt][1];
            float v1x = c[mt][nt][2], v1y = c[mt][nt][3];
            if (MODE == 1) {
                int j = col >> 1;
                float theta = powf(10000.0f, -(float)j * (1.0f / (float)HALF));
                int t0 = row & (T_ - 1);
                float s0, c0; sincosf((float)t0 * theta, &s0, &c0);
                float s1, c1; sincosf((float)(t0 + 8) * theta, &s1, &c1);
                float r0x = v0x * c0 - v0y * s0;
                float r0y = v0x * s0 + v0y * c0;
                float r1x = v1x * c1 - v1y * s1;
                float r1y = v1x * s1 + v1y * c1;
                v0x = r0x; v0y = r0y; v1x = r1x; v1y = r1y;
            } else if (MODE == 2) {
                float bx = bias[col], by = bias[col + 1];
                v0x += bx; v0y += by; v1x += bx; v1y += by;
            }
            if (MODE != 2) {   // scratch feeding tensor cores: round to tf32
                v0x = f2tff(v0x); v0y = f2tff(v0y);
                v1x = f2tff(v1x); v1y = f2tff(v1y);
            }
            *(float2*)&C[(size_t)row * N + col] = make_float2(v0x, v0y);
            *(float2*)&C[(size_t)(row + 8) * N + col] = make_float2(v1x, v1y);
        }
    }
}

// ---------------------------------------------------------------------------
// Flash attention, tf32 mma.  CTA = 128 q-rows x (batch*head), 8 warps.
// Warp w owns q-rows [w*16, w*16+16).  BN=64 keys/iter.
// Q/K/V arrive exact-tf32 (producer-rounded) -> no conversion anywhere;
// mma truncation is lossless.  Q in smem stride 68, K stride 68, V stride 72
// (all fragment-conflict-free).  cp.async 2-stage K/V pipeline.
// P redistributed C-frag -> A-frag via shfl (no smem round-trip).
// ---------------------------------------------------------------------------
#define QSTR 68
#define KSTR 68
#define VSTR 72
#define QSZ  (128 * QSTR)              // 8704 floats
#define SSZ  (64 * KSTR + 64 * VSTR)   // 8960 floats per stage

__global__ __launch_bounds__(256, 2) void attn_tc(
    const float* __restrict__ Q, const float* __restrict__ K,
    const float* __restrict__ V, float* __restrict__ O)
{
    extern __shared__ float sm[];
    float* Qs = sm;
    float* K0 = sm + QSZ;
    float* V0 = K0 + 64 * KSTR;
    float* K1 = sm + QSZ + SSZ;
    float* V1 = K1 + 64 * KSTR;

    const int tid  = threadIdx.x;
    const int lane = tid & 31;
    const int warp = tid >> 5;          // 0..7
    const int g = lane >> 2;
    const int t = lane & 3;
    const int wrow = warp * 16;

    const int qtile = blockIdx.x;       // 0..15
    const int bh = blockIdx.y;          // 0..63
    const int b = bh >> 4;
    const int h = bh & 15;
    const size_t rowbase = (size_t)b * T_;
    const int colbase = h * HDIM;

    // K/V loader: 4 threads per row, 16 floats each
    const int lrow4 = tid >> 2;         // 0..63
    const int lcb4  = (tid & 3) * 16;   // 0,16,32,48

    // ---- Stage Q tile [128 x 64] (already tf32-valued)
    {
        const int qrow = tid >> 1;          // 0..127
        const int qcb  = (tid & 1) * 32;
        const float* src = Q + (rowbase + qtile * 128 + qrow) * KDIM + colbase + qcb;
        float* dst = Qs + qrow * QSTR + qcb;
#pragma unroll
        for (int i = 0; i < 8; i++) cp16(dst + 4 * i, src + 4 * i);
        CP_COMMIT();
    }

    // ---- prologue: tile 0 -> stage 0
    {
        const size_t gb = (rowbase + lrow4) * KDIM + colbase + lcb4;
        float* kd = K0 + lrow4 * KSTR + lcb4;
        float* vd = V0 + lrow4 * VSTR + lcb4;
#pragma unroll
        for (int i = 0; i < 4; i++) {
            cp16(kd + 4 * i, K + gb + 4 * i);
            cp16(vd + 4 * i, V + gb + 4 * i);
        }
        CP_COMMIT();
    }

    float m0 = -1e30f, m1 = -1e30f, l0 = 0.0f, l1 = 0.0f;
    float o[8][4];
#pragma unroll
    for (int j = 0; j < 8; j++)
#pragma unroll
        for (int e = 0; e < 4; e++) o[j][e] = 0.0f;

    const int s0lane = 4 * g + (t >> 1);
    const int s1lane = s0lane + 2;
    const bool odd = (t & 1);

    for (int kt = 0; kt < T_ / 64; kt++) {
        const int st = kt & 1;
        float* Kc = st ? K1 : K0;
        float* Vc = st ? V1 : V0;

        CP_WAIT0();
        __syncthreads();   // tile (and Q on iter 0) arrived; prev reads done

        if (kt + 1 < T_ / 64) {
            const size_t gb = (rowbase + (kt + 1) * 64 + lrow4) * KDIM + colbase + lcb4;
            float* kd = (st ? K0 : K1) + lrow4 * KSTR + lcb4;
            float* vd = (st ? V0 : V1) + lrow4 * VSTR + lcb4;
#pragma unroll
            for (int i = 0; i < 4; i++) {
                cp16(kd + 4 * i, K + gb + 4 * i);
                cp16(vd + 4 * i, V + gb + 4 * i);
            }
        }
        CP_COMMIT();

        // ---- S = Q K^T (warp tile 16 x 64)
        float sc[8][4];
#pragma unroll
        for (int j = 0; j < 8; j++)
#pragma unroll
            for (int e = 0; e < 4; e++) sc[j][e] = 0.0f;

#pragma unroll
        for (int s = 0; s < 8; s++) {
            const float* qp = &Qs[(wrow + g) * QSTR + 8 * s + t];
            unsigned qa[4];
            qa[0] = __float_as_uint(qp[0]);
            qa[1] = __float_as_uint(qp[8 * QSTR]);
            qa[2] = __float_as_uint(qp[4]);
            qa[3] = __float_as_uint(qp[8 * QSTR + 4]);
#pragma unroll
            for (int j = 0; j < 8; j++) {
                const float* kb = &Kc[(j * 8 + g) * KSTR + 8 * s + t];
                unsigned bb[2] = { __float_as_uint(kb[0]), __float_as_uint(kb[4]) };
                mma_tf32(sc[j], qa, bb);
            }
        }
#pragma unroll
        for (int j = 0; j < 8; j++)
#pragma unroll
            for (int e = 0; e < 4; e++) sc[j][e] *= 0.125f;   // 1/sqrt(64)

        // ---- Online softmax (rows g, g+8)
        float mx0 = -1e30f, mx1 = -1e30f;
#pragma unroll
        for (int j = 0; j < 8; j++) {
            mx0 = fmaxf(mx0, fmaxf(sc[j][0], sc[j][1]));
            mx1 = fmaxf(mx1, fmaxf(sc[j][2], sc[j][3]));
        }
        mx0 = fmaxf(mx0, __shfl_xor_sync(0xffffffffu, mx0, 1));
        mx0 = fmaxf(mx0, __shfl_xor_sync(0xffffffffu, mx0, 2));
        mx1 = fmaxf(mx1, __shfl_xor_sync(0xffffffffu, mx1, 1));
        mx1 = fmaxf(mx1, __shfl_xor_sync(0xffffffffu, mx1, 2));

        float mn0 = fmaxf(m0, mx0);
        float mn1 = fmaxf(m1, mx1);
        float corr0 = __expf(m0 - mn0);
        float corr1 = __expf(m1 - mn1);

        float rs0 = 0.0f, rs1 = 0.0f;
#pragma unroll
        for (int j = 0; j < 8; j++) {
            float p0 = f2tff(__expf(sc[j][0] - mn0));
            float p1 = f2tff(__expf(sc[j][1] - mn0));
            float p2 = f2tff(__expf(sc[j][2] - mn1));
            float p3 = f2tff(__expf(sc[j][3] - mn1));
            rs0 += p0 + p1;
            rs1 += p2 + p3;
            sc[j][0] = p0; sc[j][1] = p1; sc[j][2] = p2; sc[j][3] = p3;
        }
        rs0 += __shfl_xor_sync(0xffffffffu, rs0, 1);
        rs0 += __shfl_xor_sync(0xffffffffu, rs0, 2);
        rs1 += __shfl_xor_sync(0xffffffffu, rs1, 1);
        rs1 += __shfl_xor_sync(0xffffffffu, rs1, 2);

        l0 = l0 * corr0 + rs0;
        l1 = l1 * corr1 + rs1;
#pragma unroll
        for (int j = 0; j < 8; j++) {
            o[j][0] *= corr0; o[j][1] *= corr0;
            o[j][2] *= corr1; o[j][3] *= corr1;
        }
        m0 = mn0; m1 = mn1;

        // ---- O += P V : P C-frag (keys 2t,2t+1) -> A-frag (keys t,t+4) via shfl
#pragma unroll
        for (int kk = 0; kk < 8; kk++) {
            float v00 = __shfl_sync(0xffffffffu, sc[kk][0], s0lane);
            float v01 = __shfl_sync(0xffffffffu, sc[kk][1], s0lane);
            float v02 = __shfl_sync(0xffffffffu, sc[kk][2], s0lane);
            float v03 = __shfl_sync(0xffffffffu, sc[kk][3], s0lane);
            float v10 = __shfl_sync(0xffffffffu, sc[kk][0], s1lane);
            float v11 = __shfl_sync(0xffffffffu, sc[kk][1], s1lane);
            float v12 = __shfl_sync(0xffffffffu, sc[kk][2], s1lane);
            float v13 = __shfl_sync(0xffffffffu, sc[kk][3], s1lane);
            unsigned pf[4];
            pf[0] = __float_as_uint(odd ? v01 : v00);   // P[g   ][t]
            pf[1] = __float_as_uint(odd ? v03 : v02);   // P[g+8 ][t]
            pf[2] = __float_as_uint(odd ? v11 : v10);   // P[g   ][t+4]
            pf[3] = __float_as_uint(odd ? v13 : v12);   // P[g+8 ][t+4]
#pragma unroll
            for (int j2 = 0; j2 < 8; j2++) {
                const float* vb = &Vc[(kk * 8 + t) * VSTR + j2 * 8 + g];
                unsigned bb[2] = { __float_as_uint(vb[0]), __float_as_uint(vb[4 * VSTR]) };
                mma_tf32(o[j2], pf, bb);
            }
        }
    }

    // ---- Normalize, round to tf32 (consumed by output GEMM), write out
    float inv0 = 1.0f / l0;
    float inv1 = 1.0f / l1;
    size_t orow0 = (rowbase + qtile * 128 + wrow + g) * KDIM + colbase;
    size_t orow1 = orow0 + (size_t)8 * KDIM;
#pragma unroll
    for (int j = 0; j < 8; j++) {
        int col = 8 * j + 2 * t;
        *(float2*)&O[orow0 + col] =
            make_float2(f2tff(o[j][0] * inv0), f2tff(o[j][1] * inv0));
        *(float2*)&O[orow1 + col] =
            make_float2(f2tff(o[j][2] * inv1), f2tff(o[j][3] * inv1));
    }
}

// ---------------------------------------------------------------------------
// Launcher
// ---------------------------------------------------------------------------
extern "C" void kernel_launch(void* const* d_in, const int* in_sizes, int n_in,
                              void* d_out, int out_size)
{
    const float* x  = (const float*)d_in[0];
    const float* Wq = (const float*)d_in[1];
    const float* Wk = (const float*)d_in[2];
    const float* Wv = (const float*)d_in[3];
    const float* Wu = (const float*)d_in[4];
    const float* bu = (const float*)d_in[5];
    float* out = (float*)d_out;

    float *q, *k, *v, *a, *xt, *wq, *wk, *wv, *wu;
    cudaGetSymbolAddress((void**)&q,  g_q);
    cudaGetSymbolAddress((void**)&k,  g_k);
    cudaGetSymbolAddress((void**)&v,  g_v);
    cudaGetSymbolAddress((void**)&a,  g_a);
    cudaGetSymbolAddress((void**)&xt, g_xt);
    cudaGetSymbolAddress((void**)&wq, g_wq);
    cudaGetSymbolAddress((void**)&wk, g_wk);
    cudaGetSymbolAddress((void**)&wv, g_wv);
    cudaGetSymbolAddress((void**)&wu, g_wu);

    // Pre-pass: producer-side tf32 rounding of x and weights
    {
        int n4x = ROWS * KDIM / 4;
        int n4w = KDIM * KDIM / 4;
        round_tf32_kernel<<<(n4x + 255) / 256, 256>>>((const float4*)x,  (float4*)xt, n4x);
        round_tf32_kernel<<<(n4w + 255) / 256, 256>>>((const float4*)Wq, (float4*)wq, n4w);
        round_tf32_kernel<<<(n4w + 255) / 256, 256>>>((const float4*)Wk, (float4*)wk, n4w);
        round_tf32_kernel<<<(n4w + 255) / 256, 256>>>((const float4*)Wv, (float4*)wv, n4w);
        round_tf32_kernel<<<(n4w + 255) / 256, 256>>>((const float4*)Wu, (float4*)wu, n4w);
    }

    const int gemm_smem = 4 * 128 * GS * (int)sizeof(float);   // 73728 B
    cudaFuncSetAttribute(gemm_tc<0>, cudaFuncAttributeMaxDynamicSharedMemorySize, gemm_smem);
    cudaFuncSetAttribute(gemm_tc<1>, cudaFuncAttributeMaxDynamicSharedMemorySize, gemm_smem);
    cudaFuncSetAttribute(gemm_tc<2>, cudaFuncAttributeMaxDynamicSharedMemorySize, gemm_smem);

    dim3 ggrid(KDIM / 128, ROWS / 128);  // (8, 64)

    // QKV projections; RoPE fused into Q/K epilogues; outputs tf32-rounded
    gemm_tc<1><<<ggrid, 256, gemm_smem>>>(xt, wq, nullptr, q, ROWS, KDIM, KDIM);
    gemm_tc<1><<<ggrid, 256, gemm_smem>>>(xt, wk, nullptr, k, ROWS, KDIM, KDIM);
    gemm_tc<0><<<ggrid, 256, gemm_smem>>>(xt, wv, nullptr, v, ROWS, KDIM, KDIM);

    // Attention: 128 q-rows per CTA, 8 warps
    const int attn_smem = (QSZ + 2 * SSZ) * (int)sizeof(float);  // 106496 B
    cudaFuncSetAttribute(attn_tc, cudaFuncAttributeMaxDynamicSharedMemorySize, attn_smem);
    attn_tc<<<dim3(T_ / 128, B_ * HEADS), 256, attn_smem>>>(q, k, v, a);

    // Output projection + bias (full fp32 store)
    gemm_tc<2><<<ggrid, 256, gemm_smem>>>(a, wu, bu, out, ROWS, KDIM, KDIM);
}

// round 9
// speedup vs baseline: 2.8893x; 2.2564x over previous
#include <cuda_runtime.h>
#include <cuda_fp16.h>
#include <math.h>
#include <cstdint>

// Problem constants
#define B_      4
#define T_      2048
#define KDIM    1024
#define HEADS   16
#define HDIM    64
#define ROWS    (B_ * T_)          // 8192
#define HALF    (KDIM / 2)         // 512

// ---------------------------------------------------------------------------
// Scratch (device globals: allocation-free per harness rules)
// ---------------------------------------------------------------------------
__device__ __align__(16) __half g_q[ROWS * KDIM];
__device__ __align__(16) __half g_k[ROWS * KDIM];
__device__ __align__(16) __half g_v[ROWS * KDIM];
__device__ __align__(16) __half g_a[ROWS * KDIM];
__device__ __align__(16) __half g_xt[ROWS * KDIM];
__device__ __align__(16) __half g_wq[KDIM * KDIM];
__device__ __align__(16) __half g_wk[KDIM * KDIM];
__device__ __align__(16) __half g_wv[KDIM * KDIM];
__device__ __align__(16) __half g_wu[KDIM * KDIM];

// ---------------------------------------------------------------------------
// Helpers
// ---------------------------------------------------------------------------
// mma m16n8k16 fp16 -> fp32: D = A*B + D
// A frag (4 regs, half2): a0=(g, k2t..2t+1) a1=(g+8, same) a2=(g, k2t+8..9) a3=(g+8, same)
// B frag (2 regs): b0={B[k=2t][n=g],B[k=2t+1][n=g]} b1={B[k=2t+8..9][n=g]}
// C frag: c0=(g,2t) c1=(g,2t+1) c2=(g+8,2t) c3=(g+8,2t+1)
__device__ __forceinline__ void mma_f16(float* c, const unsigned* a, const unsigned* b) {
    asm volatile(
        "mma.sync.aligned.m16n8k16.row.col.f32.f16.f16.f32 "
        "{%0,%1,%2,%3}, {%4,%5,%6,%7}, {%8,%9}, {%0,%1,%2,%3};\n"
        : "+f"(c[0]), "+f"(c[1]), "+f"(c[2]), "+f"(c[3])
        : "r"(a[0]), "r"(a[1]), "r"(a[2]), "r"(a[3]), "r"(b[0]), "r"(b[1]));
}

__device__ __forceinline__ void ldsm_x4(unsigned* r, uint32_t addr) {
    asm volatile("ldmatrix.sync.aligned.m8n8.x4.shared.b16 {%0,%1,%2,%3}, [%4];"
        : "=r"(r[0]), "=r"(r[1]), "=r"(r[2]), "=r"(r[3]) : "r"(addr));
}
__device__ __forceinline__ void ldsm_x4_t(unsigned* r, uint32_t addr) {
    asm volatile("ldmatrix.sync.aligned.m8n8.x4.trans.shared.b16 {%0,%1,%2,%3}, [%4];"
        : "=r"(r[0]), "=r"(r[1]), "=r"(r[2]), "=r"(r[3]) : "r"(addr));
}

__device__ __forceinline__ void cp16(void* dst_smem, const void* src) {
    unsigned d = (unsigned)__cvta_generic_to_shared(dst_smem);
    asm volatile("cp.async.cg.shared.global [%0], [%1], 16;\n" :: "r"(d), "l"(src));
}
#define CP_COMMIT() asm volatile("cp.async.commit_group;\n" ::: "memory")
#define CP_WAIT0()  asm volatile("cp.async.wait_group 0;\n" ::: "memory")

__device__ __forceinline__ unsigned packh2(float lo, float hi) {
    __half2 h = __floats2half2_rn(lo, hi);
    return *(unsigned*)&h;
}

// ---------------------------------------------------------------------------
// Pre-pass: round fp32 -> fp16 (producer-side; mma inputs exact thereafter)
// ---------------------------------------------------------------------------
__global__ void round_f16_kernel(const float4* __restrict__ in,
                                 __half2* __restrict__ out, int n4)
{
    int i = blockIdx.x * blockDim.x + threadIdx.x;
    if (i >= n4) return;
    float4 v = in[i];
    out[2 * i]     = __floats2half2_rn(v.x, v.y);
    out[2 * i + 1] = __floats2half2_rn(v.z, v.w);
}

// ---------------------------------------------------------------------------
// fp16 tensor-core GEMM: C[m][n] = sum_k A[m][k]*B[n][k]   (C = A @ B^T)
// MODE: 0 = fp16 store (V proj), 1 = RoPE + fp16 store (Q/K proj),
//       2 = +bias fp32 store (final output).
// 128x128x32 CTA tile, 256 threads = 8 warps (2m x 4n), warp tile 64x32.
// k-chunk = 32 halves (2 k16 steps), cp.async 2-stage pipeline.
// smem stride 40 halves (20 words): ldmatrix phase banks 20r mod 32 distinct.
// ---------------------------------------------------------------------------
#define GSH 40

template<int MODE>
__global__ __launch_bounds__(256, 2) void gemm_f16(
    const __half* __restrict__ A, const __half* __restrict__ B,
    const float* __restrict__ bias, void* __restrict__ Cv,
    int M, int N, int Kd)
{
    extern __shared__ __half smh[];
    __half* As = smh;                   // [2][128*GSH]
    __half* Bs = smh + 2 * 128 * GSH;   // [2][128*GSH]
    const uint32_t As_b = (uint32_t)__cvta_generic_to_shared(As);
    const uint32_t Bs_b = (uint32_t)__cvta_generic_to_shared(Bs);

    const int tid  = threadIdx.x;
    const int lane = tid & 31;
    const int warp = tid >> 5;
    const int g = lane >> 2;
    const int t = lane & 3;
    const int wm = warp >> 2;      // 0..1
    const int wn = warp & 3;       // 0..3
    const int bm = blockIdx.y * 128;
    const int bn = blockIdx.x * 128;

    float c[4][4][4];
#pragma unroll
    for (int i = 0; i < 4; i++)
#pragma unroll
        for (int j = 0; j < 4; j++)
#pragma unroll
            for (int e = 0; e < 4; e++) c[i][j][e] = 0.0f;

    const int lrow = tid >> 1;          // 0..127
    const int lcb  = (tid & 1) * 16;    // half offset 0 or 16
    const __half* Ap = A + (size_t)(bm + lrow) * Kd + lcb;
    const __half* Bp = B + (size_t)(bn + lrow) * Kd + lcb;
    __half* Asl = &As[lrow * GSH + lcb];
    __half* Bsl = &Bs[lrow * GSH + lcb];

    // prologue: stage 0 <- k0=0  (each thread: 16 halves A + 16 halves B)
    cp16(Asl, Ap); cp16(Asl + 8, Ap + 8);
    cp16(Bsl, Bp); cp16(Bsl + 8, Bp + 8);
    CP_COMMIT();

    // ldmatrix lane-address components (bytes)
    const int a_row = wm * 64 + (lane & 15);
    const int a_colh = (lane >> 4) << 3;
    const int b_row = wn * 32 + ((lane >> 4) << 3) + (lane & 7);
    const int b_colh = ((lane >> 3) & 1) << 3;

    for (int k0 = 0; k0 < Kd; k0 += 32) {
        const int st = (k0 >> 5) & 1;
        CP_WAIT0();
        __syncthreads();
        if (k0 + 32 < Kd) {
            const int stn = st ^ 1;
            __half* Asd = Asl + stn * 128 * GSH;
            __half* Bsd = Bsl + stn * 128 * GSH;
            cp16(Asd, Ap + k0 + 32); cp16(Asd + 8, Ap + k0 + 40);
            cp16(Bsd, Bp + k0 + 32); cp16(Bsd + 8, Bp + k0 + 40);
        }
        CP_COMMIT();

        const uint32_t Ab = As_b + st * 128 * GSH * 2;
        const uint32_t Bb = Bs_b + st * 128 * GSH * 2;
#pragma unroll
        for (int s = 0; s < 2; s++) {
            unsigned a[4][4], bf[4][2];
#pragma unroll
            for (int mt = 0; mt < 4; mt++)
                ldsm_x4(a[mt], Ab + ((a_row + mt * 16) * GSH + 16 * s + a_colh) * 2);
#pragma unroll
            for (int ntp = 0; ntp < 2; ntp++) {
                unsigned r[4];
                ldsm_x4(r, Bb + ((b_row + ntp * 16) * GSH + 16 * s + b_colh) * 2);
                bf[2 * ntp][0] = r[0]; bf[2 * ntp][1] = r[1];
                bf[2 * ntp + 1][0] = r[2]; bf[2 * ntp + 1][1] = r[3];
            }
#pragma unroll
            for (int mt = 0; mt < 4; mt++)
#pragma unroll
                for (int nt = 0; nt < 4; nt++)
                    mma_f16(c[mt][nt], a[mt], bf[nt]);
        }
        __syncthreads();
    }

    // Epilogue
#pragma unroll
    for (int mt = 0; mt < 4; mt++) {
        int row = bm + wm * 64 + mt * 16 + g;
#pragma unroll
        for (int nt = 0; nt < 4; nt++) {
            int col = bn + wn * 32 + nt * 8 + 2 * t;   // even
            float v0x = c[mt][nt][0], v0y = c[mt][nt][1];
            float v1x = c[mt][nt][2], v1y = c[mt][nt][3];
            if (MODE == 1) {
                int j = col >> 1;
                float theta = powf(10000.0f, -(float)j * (1.0f / (float)HALF));
                int t0 = row & (T_ - 1);
                float s0, c0; sincosf((float)t0 * theta, &s0, &c0);
                float s1, c1; sincosf((float)(t0 + 8) * theta, &s1, &c1);
                float r0x = v0x * c0 - v0y * s0;
                float r0y = v0x * s0 + v0y * c0;
                float r1x = v1x * c1 - v1y * s1;
                float r1y = v1x * s1 + v1y * c1;
                v0x = r0x; v0y = r0y; v1x = r1x; v1y = r1y;
            }
            if (MODE == 2) {
                float* C = (float*)Cv;
                float bx = bias[col], by = bias[col + 1];
                *(float2*)&C[(size_t)row * N + col] = make_float2(v0x + bx, v0y + by);
                *(float2*)&C[(size_t)(row + 8) * N + col] = make_float2(v1x + bx, v1y + by);
            } else {
                __half* C = (__half*)Cv;
                *(__half2*)&C[(size_t)row * N + col] = __floats2half2_rn(v0x, v0y);
                *(__half2*)&C[(size_t)(row + 8) * N + col] = __floats2half2_rn(v1x, v1y);
            }
        }
    }
}

// ---------------------------------------------------------------------------
// Flash attention, fp16 mma m16n8k16.  CTA = 128 q-rows x (batch*head),
// 8 warps x 16 q-rows.  BN=64 keys/iter.  All fragments via ldmatrix
// (V via .trans -> no transpose staging); S C-frag == PV A-frag layout,
// so P needs NO shuffles, just fp32->half2 packs.
// smem stride 72 halves (36 words): ldmatrix phase banks 4r, conflict-free.
// ---------------------------------------------------------------------------
#define QSTR 72
#define KSTR 72
#define VSTR 72
#define QSZ  (128 * QSTR)              // halves
#define SSZ  (64 * KSTR + 64 * VSTR)   // halves per stage

__global__ __launch_bounds__(256, 2) void attn_f16(
    const __half* __restrict__ Q, const __half* __restrict__ K,
    const __half* __restrict__ V, __half* __restrict__ O)
{
    extern __shared__ __half smh[];
    __half* Qs = smh;
    __half* K0 = smh + QSZ;
    __half* V0 = K0 + 64 * KSTR;
    __half* K1 = smh + QSZ + SSZ;
    __half* V1 = K1 + 64 * KSTR;
    const uint32_t Qs_b = (uint32_t)__cvta_generic_to_shared(Qs);
    const uint32_t K0_b = (uint32_t)__cvta_generic_to_shared(K0);
    const uint32_t V0_b = (uint32_t)__cvta_generic_to_shared(V0);

    const int tid  = threadIdx.x;
    const int lane = tid & 31;
    const int warp = tid >> 5;
    const int g = lane >> 2;
    const int t = lane & 3;
    const int wrow = warp * 16;

    const int qtile = blockIdx.x;       // 0..15
    const int bh = blockIdx.y;          // 0..63
    const int b = bh >> 4;
    const int h = bh & 15;
    const size_t rowbase = (size_t)b * T_;
    const int colbase = h * HDIM;

    // loaders
    const int lrow4 = tid >> 2;         // 0..63
    const int lcb4  = (tid & 3) * 16;   // half offset 0,16,32,48

    // ---- Stage Q tile [128 x 64]
    {
        const int qrow = tid >> 1;
        const int qcb  = (tid & 1) * 32;
        const __half* src = Q + (rowbase + qtile * 128 + qrow) * KDIM + colbase + qcb;
        __half* dst = Qs + qrow * QSTR + qcb;
        cp16(dst, src); cp16(dst + 8, src + 8);
        cp16(dst + 16, src + 16); cp16(dst + 24, src + 24);
        CP_COMMIT();
    }
    // ---- prologue: tile 0 -> stage 0
    {
        const size_t gb = (rowbase + lrow4) * KDIM + colbase + lcb4;
        __half* kd = K0 + lrow4 * KSTR + lcb4;
        __half* vd = V0 + lrow4 * VSTR + lcb4;
        cp16(kd, K + gb); cp16(kd + 8, K + gb + 8);
        cp16(vd, V + gb); cp16(vd + 8, V + gb + 8);
        CP_COMMIT();
    }

    float m0 = -1e30f, m1 = -1e30f, l0 = 0.0f, l1 = 0.0f;
    float o[8][4];
#pragma unroll
    for (int j = 0; j < 8; j++)
#pragma unroll
        for (int e = 0; e < 4; e++) o[j][e] = 0.0f;

    // ldmatrix lane-address components
    const int qa_row = wrow + (lane & 15);
    const int qa_colh = (lane >> 4) << 3;
    const int kb_row = ((lane >> 4) << 3) + (lane & 7);
    const int kb_colh = ((lane >> 3) & 1) << 3;
    const int vb_row = (((lane >> 3) & 1) << 3) + (lane & 7);
    const int vb_colh = (lane >> 4) << 3;

    for (int kt = 0; kt < T_ / 64; kt++) {
        const int st = kt & 1;
        const uint32_t Kb = K0_b + st * SSZ * 2;
        const uint32_t Vb = V0_b + st * SSZ * 2;

        CP_WAIT0();
        __syncthreads();

        if (kt + 1 < T_ / 64) {
            const size_t gb = (rowbase + (kt + 1) * 64 + lrow4) * KDIM + colbase + lcb4;
            __half* kd = (st ? K0 : K1) + lrow4 * KSTR + lcb4;
            __half* vd = (st ? V0 : V1) + lrow4 * VSTR + lcb4;
            cp16(kd, K + gb); cp16(kd + 8, K + gb + 8);
            cp16(vd, V + gb); cp16(vd + 8, V + gb + 8);
        }
        CP_COMMIT();

        // ---- S = Q K^T (warp tile 16 x 64): 4 d-steps x 8 key-blocks
        float sc[8][4];
#pragma unroll
        for (int j = 0; j < 8; j++)
#pragma unroll
            for (int e = 0; e < 4; e++) sc[j][e] = 0.0f;

#pragma unroll
        for (int s = 0; s < 4; s++) {
            unsigned qa[4];
            ldsm_x4(qa, Qs_b + (qa_row * QSTR + 16 * s + qa_colh) * 2);
#pragma unroll
            for (int jj = 0; jj < 4; jj++) {
                unsigned r[4];
                ldsm_x4(r, Kb + ((16 * jj + kb_row) * KSTR + 16 * s + kb_colh) * 2);
                mma_f16(sc[2 * jj], qa, r);
                mma_f16(sc[2 * jj + 1], qa, r + 2);
            }
        }
#pragma unroll
        for (int j = 0; j < 8; j++)
#pragma unroll
            for (int e = 0; e < 4; e++) sc[j][e] *= 0.125f;   // 1/sqrt(64)

        // ---- Online softmax (rows g, g+8)
        float mx0 = -1e30f, mx1 = -1e30f;
#pragma unroll
        for (int j = 0; j < 8; j++) {
            mx0 = fmaxf(mx0, fmaxf(sc[j][0], sc[j][1]));
            mx1 = fmaxf(mx1, fmaxf(sc[j][2], sc[j][3]));
        }
        mx0 = fmaxf(mx0, __shfl_xor_sync(0xffffffffu, mx0, 1));
        mx0 = fmaxf(mx0, __shfl_xor_sync(0xffffffffu, mx0, 2));
        mx1 = fmaxf(mx1, __shfl_xor_sync(0xffffffffu, mx1, 1));
        mx1 = fmaxf(mx1, __shfl_xor_sync(0xffffffffu, mx1, 2));

        float mn0 = fmaxf(m0, mx0);
        float mn1 = fmaxf(m1, mx1);
        float corr0 = __expf(m0 - mn0);
        float corr1 = __expf(m1 - mn1);

        float rs0 = 0.0f, rs1 = 0.0f;
#pragma unroll
        for (int j = 0; j < 8; j++) {
            // round P to fp16 BEFORE the l-sum (consistency with PV mma)
            float p0 = __half2float(__float2half_rn(__expf(sc[j][0] - mn0)));
            float p1 = __half2float(__float2half_rn(__expf(sc[j][1] - mn0)));
            float p2 = __half2float(__float2half_rn(__expf(sc[j][2] - mn1)));
            float p3 = __half2float(__float2half_rn(__expf(sc[j][3] - mn1)));
            rs0 += p0 + p1;
            rs1 += p2 + p3;
            sc[j][0] = p0; sc[j][1] = p1; sc[j][2] = p2; sc[j][3] = p3;
        }
        rs0 += __shfl_xor_sync(0xffffffffu, rs0, 1);
        rs0 += __shfl_xor_sync(0xffffffffu, rs0, 2);
        rs1 += __shfl_xor_sync(0xffffffffu, rs1, 1);
        rs1 += __shfl_xor_sync(0xffffffffu, rs1, 2);

        l0 = l0 * corr0 + rs0;
        l1 = l1 * corr1 + rs1;
#pragma unroll
        for (int j = 0; j < 8; j++) {
            o[j][0] *= corr0; o[j][1] *= corr0;
            o[j][2] *= corr1; o[j][3] *= corr1;
        }
        m0 = mn0; m1 = mn1;

        // ---- O += P V : S C-frag == PV A-frag (no shuffles, just packs)
        unsigned pf[4][4];
#pragma unroll
        for (int s2 = 0; s2 < 4; s2++) {
            pf[s2][0] = packh2(sc[2 * s2][0], sc[2 * s2][1]);
            pf[s2][1] = packh2(sc[2 * s2][2], sc[2 * s2][3]);
            pf[s2][2] = packh2(sc[2 * s2 + 1][0], sc[2 * s2 + 1][1]);
            pf[s2][3] = packh2(sc[2 * s2 + 1][2], sc[2 * s2 + 1][3]);
        }
#pragma unroll
        for (int s2 = 0; s2 < 4; s2++) {
#pragma unroll
            for (int jj2 = 0; jj2 < 4; jj2++) {
                unsigned r[4];
                ldsm_x4_t(r, Vb + ((16 * s2 + vb_row) * VSTR + 16 * jj2 + vb_colh) * 2);
                mma_f16(o[2 * jj2], pf[s2], r);
                mma_f16(o[2 * jj2 + 1], pf[s2], r + 2);
            }
        }
    }

    // ---- Normalize, store fp16 ([b*t][h*64])
    float inv0 = 1.0f / l0;
    float inv1 = 1.0f / l1;
    size_t orow0 = (rowbase + qtile * 128 + wrow + g) * KDIM + colbase;
    size_t orow1 = orow0 + (size_t)8 * KDIM;
#pragma unroll
    for (int j = 0; j < 8; j++) {
        int col = 8 * j + 2 * t;
        *(__half2*)&O[orow0 + col] = __floats2half2_rn(o[j][0] * inv0, o[j][1] * inv0);
        *(__half2*)&O[orow1 + col] = __floats2half2_rn(o[j][2] * inv1, o[j][3] * inv1);
    }
}

// ---------------------------------------------------------------------------
// Launcher
// ---------------------------------------------------------------------------
extern "C" void kernel_launch(void* const* d_in, const int* in_sizes, int n_in,
                              void* d_out, int out_size)
{
    const float* x  = (const float*)d_in[0];
    const float* Wq = (const float*)d_in[1];
    const float* Wk = (const float*)d_in[2];
    const float* Wv = (const float*)d_in[3];
    const float* Wu = (const float*)d_in[4];
    const float* bu = (const float*)d_in[5];
    float* out = (float*)d_out;

    __half *q, *k, *v, *a, *xt, *wq, *wk, *wv, *wu;
    cudaGetSymbolAddress((void**)&q,  g_q);
    cudaGetSymbolAddress((void**)&k,  g_k);
    cudaGetSymbolAddress((void**)&v,  g_v);
    cudaGetSymbolAddress((void**)&a,  g_a);
    cudaGetSymbolAddress((void**)&xt, g_xt);
    cudaGetSymbolAddress((void**)&wq, g_wq);
    cudaGetSymbolAddress((void**)&wk, g_wk);
    cudaGetSymbolAddress((void**)&wv, g_wv);
    cudaGetSymbolAddress((void**)&wu, g_wu);

    // Pre-pass: producer-side fp16 rounding of x and weights
    {
        int n4x = ROWS * KDIM / 4;
        int n4w = KDIM * KDIM / 4;
        round_f16_kernel<<<(n4x + 255) / 256, 256>>>((const float4*)x,  (__half2*)xt, n4x);
        round_f16_kernel<<<(n4w + 255) / 256, 256>>>((const float4*)Wq, (__half2*)wq, n4w);
        round_f16_kernel<<<(n4w + 255) / 256, 256>>>((const float4*)Wk, (__half2*)wk, n4w);
        round_f16_kernel<<<(n4w + 255) / 256, 256>>>((const float4*)Wv, (__half2*)wv, n4w);
        round_f16_kernel<<<(n4w + 255) / 256, 256>>>((const float4*)Wu, (__half2*)wu, n4w);
    }

    const int gemm_smem = 4 * 128 * GSH * (int)sizeof(__half);   // 40960 B
    cudaFuncSetAttribute(gemm_f16<0>, cudaFuncAttributeMaxDynamicSharedMemorySize, gemm_smem);
    cudaFuncSetAttribute(gemm_f16<1>, cudaFuncAttributeMaxDynamicSharedMemorySize, gemm_smem);
    cudaFuncSetAttribute(gemm_f16<2>, cudaFuncAttributeMaxDynamicSharedMemorySize, gemm_smem);

    dim3 ggrid(KDIM / 128, ROWS / 128);  // (8, 64)

    // QKV projections; RoPE fused into Q/K epilogues; fp16 scratch out
    gemm_f16<1><<<ggrid, 256, gemm_smem>>>(xt, wq, nullptr, q, ROWS, KDIM, KDIM);
    gemm_f16<1><<<ggrid, 256, gemm_smem>>>(xt, wk, nullptr, k, ROWS, KDIM, KDIM);
    gemm_f16<0><<<ggrid, 256, gemm_smem>>>(xt, wv, nullptr, v, ROWS, KDIM, KDIM);

    // Attention: 128 q-rows per CTA, 8 warps
    const int attn_smem = (QSZ + 2 * SSZ) * (int)sizeof(__half);  // 55296 B
    cudaFuncSetAttribute(attn_f16, cudaFuncAttributeMaxDynamicSharedMemorySize, attn_smem);
    attn_f16<<<dim3(T_ / 128, B_ * HEADS), 256, attn_smem>>>(q, k, v, a);

    // Output projection + bias (fp32 store)
    gemm_f16<2><<<ggrid, 256, gemm_smem>>>(a, wu, bu, out, ROWS, KDIM, KDIM);
}

// round 10
// speedup vs baseline: 3.0083x; 1.0412x over previous
#include <cuda_runtime.h>
#include <cuda_fp16.h>
#include <math.h>
#include <cstdint>

// Problem constants
#define B_      4
#define T_      2048
#define KDIM    1024
#define HEADS   16
#define HDIM    64
#define ROWS    (B_ * T_)          // 8192
#define HALF    (KDIM / 2)         // 512

// ---------------------------------------------------------------------------
// Scratch (device globals: allocation-free per harness rules)
// ---------------------------------------------------------------------------
__device__ __align__(16) __half g_q[ROWS * KDIM];
__device__ __align__(16) __half g_k[ROWS * KDIM];
__device__ __align__(16) __half g_v[ROWS * KDIM];
__device__ __align__(16) __half g_a[ROWS * KDIM];
__device__ __align__(16) __half g_xt[ROWS * KDIM];
__device__ __align__(16) __half g_wq[KDIM * KDIM];
__device__ __align__(16) __half g_wk[KDIM * KDIM];
__device__ __align__(16) __half g_wv[KDIM * KDIM];
__device__ __align__(16) __half g_wu[KDIM * KDIM];

// ---------------------------------------------------------------------------
// Helpers
// ---------------------------------------------------------------------------
__device__ __forceinline__ void mma_f16(float* c, const unsigned* a, const unsigned* b) {
    asm volatile(
        "mma.sync.aligned.m16n8k16.row.col.f32.f16.f16.f32 "
        "{%0,%1,%2,%3}, {%4,%5,%6,%7}, {%8,%9}, {%0,%1,%2,%3};\n"
        : "+f"(c[0]), "+f"(c[1]), "+f"(c[2]), "+f"(c[3])
        : "r"(a[0]), "r"(a[1]), "r"(a[2]), "r"(a[3]), "r"(b[0]), "r"(b[1]));
}

__device__ __forceinline__ void ldsm_x4(unsigned* r, uint32_t addr) {
    asm volatile("ldmatrix.sync.aligned.m8n8.x4.shared.b16 {%0,%1,%2,%3}, [%4];"
        : "=r"(r[0]), "=r"(r[1]), "=r"(r[2]), "=r"(r[3]) : "r"(addr));
}
__device__ __forceinline__ void ldsm_x4_t(unsigned* r, uint32_t addr) {
    asm volatile("ldmatrix.sync.aligned.m8n8.x4.trans.shared.b16 {%0,%1,%2,%3}, [%4];"
        : "=r"(r[0]), "=r"(r[1]), "=r"(r[2]), "=r"(r[3]) : "r"(addr));
}

__device__ __forceinline__ void cp16(void* dst_smem, const void* src) {
    unsigned d = (unsigned)__cvta_generic_to_shared(dst_smem);
    asm volatile("cp.async.cg.shared.global [%0], [%1], 16;\n" :: "r"(d), "l"(src));
}
#define CP_COMMIT() asm volatile("cp.async.commit_group;\n" ::: "memory")
#define CP_WAIT1()  asm volatile("cp.async.wait_group 1;\n" ::: "memory")

__device__ __forceinline__ unsigned packh2(float lo, float hi) {
    __half2 h = __floats2half2_rn(lo, hi);
    return *(unsigned*)&h;
}
__device__ __forceinline__ float ex2f(float x) {
    float y;
    asm("ex2.approx.f32 %0, %1;" : "=f"(y) : "f"(x));
    return y;
}

#define SOFTMAX_SCALE 0.1803368801111244f   // 0.125 * log2(e)

// ---------------------------------------------------------------------------
// Pre-pass (single launch): z=0 rounds x, z=1..4 round the four weights
// ---------------------------------------------------------------------------
__global__ void round_all(const float4* __restrict__ x,
                          const float4* __restrict__ Wq,
                          const float4* __restrict__ Wk,
                          const float4* __restrict__ Wv,
                          const float4* __restrict__ Wu)
{
    const int z = blockIdx.z;
    const float4* in;
    __half2* out;
    int n4;
    if (z == 0)      { in = x;  out = (__half2*)g_xt; n4 = ROWS * KDIM / 4; }
    else if (z == 1) { in = Wq; out = (__half2*)g_wq; n4 = KDIM * KDIM / 4; }
    else if (z == 2) { in = Wk; out = (__half2*)g_wk; n4 = KDIM * KDIM / 4; }
    else if (z == 3) { in = Wv; out = (__half2*)g_wv; n4 = KDIM * KDIM / 4; }
    else             { in = Wu; out = (__half2*)g_wu; n4 = KDIM * KDIM / 4; }
    int i = blockIdx.x * blockDim.x + threadIdx.x;
    if (i >= n4) return;
    float4 v = in[i];
    out[2 * i]     = __floats2half2_rn(v.x, v.y);
    out[2 * i + 1] = __floats2half2_rn(v.z, v.w);
}

// ---------------------------------------------------------------------------
// fp16 GEMM core geometry (shared by QKV-fused and output kernels):
// 128x128x32 CTA tile, 256 threads = 8 warps (2m x 4n), warp tile 64x32,
// 3-stage cp.async pipeline (wait_group 1), smem stride 40 halves.
// ---------------------------------------------------------------------------
#define GSH 40
#define GSTGH (2 * 128 * GSH)          // halves per stage (A+B)
#define GSTGB (GSTGH * 2)              // bytes per stage
#define G5SMEM (3 * GSTGB)             // 61440 B

// Fused QKV projection: grid (8, 64, 3).  z selects weight/output/RoPE.
__global__ __launch_bounds__(256, 2) void gemm_qkv()
{
    extern __shared__ __half smh[];
    const uint32_t base_b = (uint32_t)__cvta_generic_to_shared(smh);

    const int z = blockIdx.z;
    const __half* A = g_xt;
    const __half* B = (z == 0) ? g_wq : (z == 1) ? g_wk : g_wv;
    __half* C = (z == 0) ? g_q : (z == 1) ? g_k : g_v;
    const bool do_rope = (z < 2);

    const int tid  = threadIdx.x;
    const int lane = tid & 31;
    const int warp = tid >> 5;
    const int g = lane >> 2;
    const int t = lane & 3;
    const int wm = warp >> 2;
    const int wn = warp & 3;
    const int bm = blockIdx.y * 128;
    const int bn = blockIdx.x * 128;

    float c[4][4][4];
#pragma unroll
    for (int i = 0; i < 4; i++)
#pragma unroll
        for (int j = 0; j < 4; j++)
#pragma unroll
            for (int e = 0; e < 4; e++) c[i][j][e] = 0.0f;

    const int lrow = tid >> 1;
    const int lcb  = (tid & 1) * 16;
    const __half* Ap = A + (size_t)(bm + lrow) * KDIM + lcb;
    const __half* Bp = B + (size_t)(bn + lrow) * KDIM + lcb;

    auto fill = [&](int ch, int s) {
        __half* Asd = smh + s * GSTGH + lrow * GSH + lcb;
        __half* Bsd = Asd + 128 * GSH;
        cp16(Asd, Ap + ch * 32); cp16(Asd + 8, Ap + ch * 32 + 8);
        cp16(Bsd, Bp + ch * 32); cp16(Bsd + 8, Bp + ch * 32 + 8);
    };

    fill(0, 0); CP_COMMIT();
    fill(1, 1); CP_COMMIT();

    const int a_row = wm * 64 + (lane & 15);
    const int a_colh = (lane >> 4) << 3;
    const int b_row = wn * 32 + ((lane >> 4) << 3) + (lane & 7);
    const int b_colh = ((lane >> 3) & 1) << 3;

    const int NCH = KDIM / 32;           // 32
    for (int i = 0; i < NCH; i++) {
        const int s = i - (i / 3) * 3;   // i % 3
        CP_WAIT1();
        __syncthreads();
        const int j = i + 2;
        if (j < NCH) fill(j, j - (j / 3) * 3);
        CP_COMMIT();

        const uint32_t Ab = base_b + s * GSTGB;
        const uint32_t Bb = Ab + 128 * GSH * 2;
#pragma unroll
        for (int ks = 0; ks < 2; ks++) {
            unsigned a[4][4], bf[4][2];
#pragma unroll
            for (int mt = 0; mt < 4; mt++)
                ldsm_x4(a[mt], Ab + ((a_row + mt * 16) * GSH + 16 * ks + a_colh) * 2);
#pragma unroll
            for (int ntp = 0; ntp < 2; ntp++) {
                unsigned r[4];
                ldsm_x4(r, Bb + ((b_row + ntp * 16) * GSH + 16 * ks + b_colh) * 2);
                bf[2 * ntp][0] = r[0]; bf[2 * ntp][1] = r[1];
                bf[2 * ntp + 1][0] = r[2]; bf[2 * ntp + 1][1] = r[3];
            }
#pragma unroll
            for (int mt = 0; mt < 4; mt++)
#pragma unroll
                for (int nt = 0; nt < 4; nt++)
                    mma_f16(c[mt][nt], a[mt], bf[nt]);
        }
    }

    // Epilogue: RoPE (z<2) or plain, fp16 store
#pragma unroll
    for (int mt = 0; mt < 4; mt++) {
        int row = bm + wm * 64 + mt * 16 + g;
#pragma unroll
        for (int nt = 0; nt < 4; nt++) {
            int col = bn + wn * 32 + nt * 8 + 2 * t;
            float v0x = c[mt][nt][0], v0y = c[mt][nt][1];
            float v1x = c[mt][nt][2], v1y = c[mt][nt][3];
            if (do_rope) {
                int j = col >> 1;
                float theta = powf(10000.0f, -(float)j * (1.0f / (float)HALF));
                int t0 = row & (T_ - 1);
                float s0, c0; sincosf((float)t0 * theta, &s0, &c0);
                float s1, c1; sincosf((float)(t0 + 8) * theta, &s1, &c1);
                float r0x = v0x * c0 - v0y * s0;
                float r0y = v0x * s0 + v0y * c0;
                float r1x = v1x * c1 - v1y * s1;
                float r1y = v1x * s1 + v1y * c1;
                v0x = r0x; v0y = r0y; v1x = r1x; v1y = r1y;
            }
            *(__half2*)&C[(size_t)row * KDIM + col] = __floats2half2_rn(v0x, v0y);
            *(__half2*)&C[(size_t)(row + 8) * KDIM + col] = __floats2half2_rn(v1x, v1y);
        }
    }
}

// Output projection: fp32 store + bias
__global__ __launch_bounds__(256, 2) void gemm_out(
    const float* __restrict__ bias, float* __restrict__ C)
{
    extern __shared__ __half smh[];
    const uint32_t base_b = (uint32_t)__cvta_generic_to_shared(smh);

    const int tid  = threadIdx.x;
    const int lane = tid & 31;
    const int warp = tid >> 5;
    const int g = lane >> 2;
    const int t = lane & 3;
    const int wm = warp >> 2;
    const int wn = warp & 3;
    const int bm = blockIdx.y * 128;
    const int bn = blockIdx.x * 128;

    float c[4][4][4];
#pragma unroll
    for (int i = 0; i < 4; i++)
#pragma unroll
        for (int j = 0; j < 4; j++)
#pragma unroll
            for (int e = 0; e < 4; e++) c[i][j][e] = 0.0f;

    const int lrow = tid >> 1;
    const int lcb  = (tid & 1) * 16;
    const __half* Ap = g_a  + (size_t)(bm + lrow) * KDIM + lcb;
    const __half* Bp = g_wu + (size_t)(bn + lrow) * KDIM + lcb;

    auto fill = [&](int ch, int s) {
        __half* Asd = smh + s * GSTGH + lrow * GSH + lcb;
        __half* Bsd = Asd + 128 * GSH;
        cp16(Asd, Ap + ch * 32); cp16(Asd + 8, Ap + ch * 32 + 8);
        cp16(Bsd, Bp + ch * 32); cp16(Bsd + 8, Bp + ch * 32 + 8);
    };

    fill(0, 0); CP_COMMIT();
    fill(1, 1); CP_COMMIT();

    const int a_row = wm * 64 + (lane & 15);
    const int a_colh = (lane >> 4) << 3;
    const int b_row = wn * 32 + ((lane >> 4) << 3) + (lane & 7);
    const int b_colh = ((lane >> 3) & 1) << 3;

    const int NCH = KDIM / 32;
    for (int i = 0; i < NCH; i++) {
        const int s = i - (i / 3) * 3;
        CP_WAIT1();
        __syncthreads();
        const int j = i + 2;
        if (j < NCH) fill(j, j - (j / 3) * 3);
        CP_COMMIT();

        const uint32_t Ab = base_b + s * GSTGB;
        const uint32_t Bb = Ab + 128 * GSH * 2;
#pragma unroll
        for (int ks = 0; ks < 2; ks++) {
            unsigned a[4][4], bf[4][2];
#pragma unroll
            for (int mt = 0; mt < 4; mt++)
                ldsm_x4(a[mt], Ab + ((a_row + mt * 16) * GSH + 16 * ks + a_colh) * 2);
#pragma unroll
            for (int ntp = 0; ntp < 2; ntp++) {
                unsigned r[4];
                ldsm_x4(r, Bb + ((b_row + ntp * 16) * GSH + 16 * ks + b_colh) * 2);
                bf[2 * ntp][0] = r[0]; bf[2 * ntp][1] = r[1];
                bf[2 * ntp + 1][0] = r[2]; bf[2 * ntp + 1][1] = r[3];
            }
#pragma unroll
            for (int mt = 0; mt < 4; mt++)
#pragma unroll
                for (int nt = 0; nt < 4; nt++)
                    mma_f16(c[mt][nt], a[mt], bf[nt]);
        }
    }

#pragma unroll
    for (int mt = 0; mt < 4; mt++) {
        int row = bm + wm * 64 + mt * 16 + g;
#pragma unroll
        for (int nt = 0; nt < 4; nt++) {
            int col = bn + wn * 32 + nt * 8 + 2 * t;
            float bx = bias[col], by = bias[col + 1];
            *(float2*)&C[(size_t)row * KDIM + col] =
                make_float2(c[mt][nt][0] + bx, c[mt][nt][1] + by);
            *(float2*)&C[(size_t)(row + 8) * KDIM + col] =
                make_float2(c[mt][nt][2] + bx, c[mt][nt][3] + by);
        }
    }
}

// ---------------------------------------------------------------------------
// Flash attention, fp16 mma m16n8k16, 3-stage K/V cp.async pipeline.
// CTA = 128 q-rows x (batch*head), 8 warps x 16 q-rows, BN=64.
// Softmax in log2 domain (ex2.approx).  S C-frag == PV A-frag (no shuffles).
// ---------------------------------------------------------------------------
#define QSTR 72
#define KSTR 72
#define VSTR 72
#define QSZ  (128 * QSTR)              // halves
#define SSZ  (64 * KSTR + 64 * VSTR)   // halves per K/V stage

__global__ __launch_bounds__(256, 2) void attn_f16(
    const __half* __restrict__ Q, const __half* __restrict__ K,
    const __half* __restrict__ V, __half* __restrict__ O)
{
    extern __shared__ __half smh[];
    __half* Qs = smh;
    __half* KV = smh + QSZ;            // 3 stages of [K(64xKSTR) | V(64xVSTR)]
    const uint32_t Qs_b = (uint32_t)__cvta_generic_to_shared(Qs);
    const uint32_t KV_b = (uint32_t)__cvta_generic_to_shared(KV);

    const int tid  = threadIdx.x;
    const int lane = tid & 31;
    const int warp = tid >> 5;
    const int g = lane >> 2;
    const int t = lane & 3;
    const int wrow = warp * 16;

    const int qtile = blockIdx.x;
    const int bh = blockIdx.y;
    const int b = bh >> 4;
    const int h = bh & 15;
    const size_t rowbase = (size_t)b * T_;
    const int colbase = h * HDIM;

    const int lrow4 = tid >> 2;
    const int lcb4  = (tid & 3) * 16;

    auto fill_kv = [&](int kt, int s) {
        const size_t gb = (rowbase + kt * 64 + lrow4) * KDIM + colbase + lcb4;
        __half* kd = KV + s * SSZ + lrow4 * KSTR + lcb4;
        __half* vd = kd + 64 * KSTR;
        cp16(kd, K + gb); cp16(kd + 8, K + gb + 8);
        cp16(vd, V + gb); cp16(vd + 8, V + gb + 8);
    };

    // ---- Stage Q tile [128 x 64]
    {
        const int qrow = tid >> 1;
        const int qcb  = (tid & 1) * 32;
        const __half* src = Q + (rowbase + qtile * 128 + qrow) * KDIM + colbase + qcb;
        __half* dst = Qs + qrow * QSTR + qcb;
        cp16(dst, src); cp16(dst + 8, src + 8);
        cp16(dst + 16, src + 16); cp16(dst + 24, src + 24);
        CP_COMMIT();
    }
    fill_kv(0, 0); CP_COMMIT();
    fill_kv(1, 1); CP_COMMIT();

    float m0 = -1e30f, m1 = -1e30f, l0 = 0.0f, l1 = 0.0f;
    float o[8][4];
#pragma unroll
    for (int j = 0; j < 8; j++)
#pragma unroll
        for (int e = 0; e < 4; e++) o[j][e] = 0.0f;

    const int qa_row = wrow + (lane & 15);
    const int qa_colh = (lane >> 4) << 3;
    const int kb_row = ((lane >> 4) << 3) + (lane & 7);
    const int kb_colh = ((lane >> 3) & 1) << 3;
    const int vb_row = (((lane >> 3) & 1) << 3) + (lane & 7);
    const int vb_colh = (lane >> 4) << 3;

    const int NT = T_ / 64;              // 32
    for (int kt = 0; kt < NT; kt++) {
        const int s = kt - (kt / 3) * 3;
        const uint32_t Kb = KV_b + s * SSZ * 2;
        const uint32_t Vb = Kb + 64 * KSTR * 2;

        CP_WAIT1();
        __syncthreads();
        const int jn = kt + 2;
        if (jn < NT) fill_kv(jn, jn - (jn / 3) * 3);
        CP_COMMIT();

        // ---- S = Q K^T (warp tile 16 x 64)
        float sc[8][4];
#pragma unroll
        for (int j = 0; j < 8; j++)
#pragma unroll
            for (int e = 0; e < 4; e++) sc[j][e] = 0.0f;

#pragma unroll
        for (int ds = 0; ds < 4; ds++) {
            unsigned qa[4];
            ldsm_x4(qa, Qs_b + (qa_row * QSTR + 16 * ds + qa_colh) * 2);
#pragma unroll
            for (int jj = 0; jj < 4; jj++) {
                unsigned r[4];
                ldsm_x4(r, Kb + ((16 * jj + kb_row) * KSTR + 16 * ds + kb_colh) * 2);
                mma_f16(sc[2 * jj], qa, r);
                mma_f16(sc[2 * jj + 1], qa, r + 2);
            }
        }
#pragma unroll
        for (int j = 0; j < 8; j++)
#pragma unroll
            for (int e = 0; e < 4; e++) sc[j][e] *= SOFTMAX_SCALE;  // log2 domain

        // ---- Online softmax (rows g, g+8), exp via ex2
        float mx0 = -1e30f, mx1 = -1e30f;
#pragma unroll
        for (int j = 0; j < 8; j++) {
            mx0 = fmaxf(mx0, fmaxf(sc[j][0], sc[j][1]));
            mx1 = fmaxf(mx1, fmaxf(sc[j][2], sc[j][3]));
        }
        mx0 = fmaxf(mx0, __shfl_xor_sync(0xffffffffu, mx0, 1));
        mx0 = fmaxf(mx0, __shfl_xor_sync(0xffffffffu, mx0, 2));
        mx1 = fmaxf(mx1, __shfl_xor_sync(0xffffffffu, mx1, 1));
        mx1 = fmaxf(mx1, __shfl_xor_sync(0xffffffffu, mx1, 2));

        float mn0 = fmaxf(m0, mx0);
        float mn1 = fmaxf(m1, mx1);
        float corr0 = ex2f(m0 - mn0);
        float corr1 = ex2f(m1 - mn1);

        float rs0 = 0.0f, rs1 = 0.0f;
#pragma unroll
        for (int j = 0; j < 8; j++) {
            float p0 = __half2float(__float2half_rn(ex2f(sc[j][0] - mn0)));
            float p1 = __half2float(__float2half_rn(ex2f(sc[j][1] - mn0)));
            float p2 = __half2float(__float2half_rn(ex2f(sc[j][2] - mn1)));
            float p3 = __half2float(__float2half_rn(ex2f(sc[j][3] - mn1)));
            rs0 += p0 + p1;
            rs1 += p2 + p3;
            sc[j][0] = p0; sc[j][1] = p1; sc[j][2] = p2; sc[j][3] = p3;
        }
        rs0 += __shfl_xor_sync(0xffffffffu, rs0, 1);
        rs0 += __shfl_xor_sync(0xffffffffu, rs0, 2);
        rs1 += __shfl_xor_sync(0xffffffffu, rs1, 1);
        rs1 += __shfl_xor_sync(0xffffffffu, rs1, 2);

        l0 = l0 * corr0 + rs0;
        l1 = l1 * corr1 + rs1;
#pragma unroll
        for (int j = 0; j < 8; j++) {
            o[j][0] *= corr0; o[j][1] *= corr0;
            o[j][2] *= corr1; o[j][3] *= corr1;
        }
        m0 = mn0; m1 = mn1;

        // ---- O += P V (S C-frag == PV A-frag; V via ldmatrix.trans)
        unsigned pf[4][4];
#pragma unroll
        for (int s2 = 0; s2 < 4; s2++) {
            pf[s2][0] = packh2(sc[2 * s2][0], sc[2 * s2][1]);
            pf[s2][1] = packh2(sc[2 * s2][2], sc[2 * s2][3]);
            pf[s2][2] = packh2(sc[2 * s2 + 1][0], sc[2 * s2 + 1][1]);
            pf[s2][3] = packh2(sc[2 * s2 + 1][2], sc[2 * s2 + 1][3]);
        }
#pragma unroll
        for (int s2 = 0; s2 < 4; s2++) {
#pragma unroll
            for (int jj2 = 0; jj2 < 4; jj2++) {
                unsigned r[4];
                ldsm_x4_t(r, Vb + ((16 * s2 + vb_row) * VSTR + 16 * jj2 + vb_colh) * 2);
                mma_f16(o[2 * jj2], pf[s2], r);
                mma_f16(o[2 * jj2 + 1], pf[s2], r + 2);
            }
        }
    }

    // ---- Normalize, store fp16 ([b*t][h*64])
    float inv0 = 1.0f / l0;
    float inv1 = 1.0f / l1;
    size_t orow0 = (rowbase + qtile * 128 + wrow + g) * KDIM + colbase;
    size_t orow1 = orow0 + (size_t)8 * KDIM;
#pragma unroll
    for (int j = 0; j < 8; j++) {
        int col = 8 * j + 2 * t;
        *(__half2*)&O[orow0 + col] = __floats2half2_rn(o[j][0] * inv0, o[j][1] * inv0);
        *(__half2*)&O[orow1 + col] = __floats2half2_rn(o[j][2] * inv1, o[j][3] * inv1);
    }
}

// ---------------------------------------------------------------------------
// Launcher
// ---------------------------------------------------------------------------
extern "C" void kernel_launch(void* const* d_in, const int* in_sizes, int n_in,
                              void* d_out, int out_size)
{
    const float* x  = (const float*)d_in[0];
    const float* Wq = (const float*)d_in[1];
    const float* Wk = (const float*)d_in[2];
    const float* Wv = (const float*)d_in[3];
    const float* Wu = (const float*)d_in[4];
    const float* bu = (const float*)d_in[5];
    float* out = (float*)d_out;

    __half *q, *k, *v, *a;
    cudaGetSymbolAddress((void**)&q, g_q);
    cudaGetSymbolAddress((void**)&k, g_k);
    cudaGetSymbolAddress((void**)&v, g_v);
    cudaGetSymbolAddress((void**)&a, g_a);

    // Pre-pass: one launch rounds x + all 4 weights to fp16
    {
        int blocks_x = (ROWS * KDIM / 4 + 255) / 256;   // 8192
        round_all<<<dim3(blocks_x, 1, 5), 256>>>(
            (const float4*)x, (const float4*)Wq, (const float4*)Wk,
            (const float4*)Wv, (const float4*)Wu);
    }

    cudaFuncSetAttribute(gemm_qkv, cudaFuncAttributeMaxDynamicSharedMemorySize, G5SMEM);
    cudaFuncSetAttribute(gemm_out, cudaFuncAttributeMaxDynamicSharedMemorySize, G5SMEM);

    // Fused QKV projections (one launch, grid.z selects Q/K/V)
    gemm_qkv<<<dim3(KDIM / 128, ROWS / 128, 3), 256, G5SMEM>>>();

    // Attention
    const int attn_smem = (QSZ + 3 * SSZ) * (int)sizeof(__half);  // 73728 B
    cudaFuncSetAttribute(attn_f16, cudaFuncAttributeMaxDynamicSharedMemorySize, attn_smem);
    attn_f16<<<dim3(T_ / 128, B_ * HEADS), 256, attn_smem>>>(q, k, v, a);

    // Output projection + bias (fp32 store)
    gemm_out<<<dim3(KDIM / 128, ROWS / 128), 256, G5SMEM>>>(bu, out);
}

// round 11
// speedup vs baseline: 3.0673x; 1.0196x over previous
#include <cuda_runtime.h>
#include <cuda_fp16.h>
#include <math.h>
#include <cstdint>

// Problem constants
#define B_      4
#define T_      2048
#define KDIM    1024
#define HEADS   16
#define HDIM    64
#define ROWS    (B_ * T_)          // 8192
#define HALF    (KDIM / 2)         // 512

// ---------------------------------------------------------------------------
// Scratch (device globals: allocation-free per harness rules)
// ---------------------------------------------------------------------------
__device__ __align__(16) __half g_q[ROWS * KDIM];
__device__ __align__(16) __half g_k[ROWS * KDIM];
__device__ __align__(16) __half g_v[ROWS * KDIM];
__device__ __align__(16) __half g_a[ROWS * KDIM];
__device__ __align__(16) __half g_xt[ROWS * KDIM];
__device__ __align__(16) __half g_wq[KDIM * KDIM];
__device__ __align__(16) __half g_wk[KDIM * KDIM];
__device__ __align__(16) __half g_wv[KDIM * KDIM];
__device__ __align__(16) __half g_wu[KDIM * KDIM];

// ---------------------------------------------------------------------------
// Helpers
// ---------------------------------------------------------------------------
__device__ __forceinline__ void mma_f16(float* c, const unsigned* a, const unsigned* b) {
    asm volatile(
        "mma.sync.aligned.m16n8k16.row.col.f32.f16.f16.f32 "
        "{%0,%1,%2,%3}, {%4,%5,%6,%7}, {%8,%9}, {%0,%1,%2,%3};\n"
        : "+f"(c[0]), "+f"(c[1]), "+f"(c[2]), "+f"(c[3])
        : "r"(a[0]), "r"(a[1]), "r"(a[2]), "r"(a[3]), "r"(b[0]), "r"(b[1]));
}

__device__ __forceinline__ void ldsm_x4(unsigned* r, uint32_t addr) {
    asm volatile("ldmatrix.sync.aligned.m8n8.x4.shared.b16 {%0,%1,%2,%3}, [%4];"
        : "=r"(r[0]), "=r"(r[1]), "=r"(r[2]), "=r"(r[3]) : "r"(addr));
}
__device__ __forceinline__ void ldsm_x4_t(unsigned* r, uint32_t addr) {
    asm volatile("ldmatrix.sync.aligned.m8n8.x4.trans.shared.b16 {%0,%1,%2,%3}, [%4];"
        : "=r"(r[0]), "=r"(r[1]), "=r"(r[2]), "=r"(r[3]) : "r"(addr));
}

__device__ __forceinline__ void cp16(void* dst_smem, const void* src) {
    unsigned d = (unsigned)__cvta_generic_to_shared(dst_smem);
    asm volatile("cp.async.cg.shared.global [%0], [%1], 16;\n" :: "r"(d), "l"(src));
}
#define CP_COMMIT() asm volatile("cp.async.commit_group;\n" ::: "memory")
#define CP_WAIT2()  asm volatile("cp.async.wait_group 2;\n" ::: "memory")
#define CP_WAIT3()  asm volatile("cp.async.wait_group 3;\n" ::: "memory")

__device__ __forceinline__ float ex2f(float x) {
    float y;
    asm("ex2.approx.f32 %0, %1;" : "=f"(y) : "f"(x));
    return y;
}

#define SOFTMAX_SCALE 0.1803368801111244f   // 0.125 * log2(e)

// ---------------------------------------------------------------------------
// Pre-pass (single launch): z=0 rounds x, z=1..4 round the four weights
// ---------------------------------------------------------------------------
__global__ void round_all(const float4* __restrict__ x,
                          const float4* __restrict__ Wq,
                          const float4* __restrict__ Wk,
                          const float4* __restrict__ Wv,
                          const float4* __restrict__ Wu)
{
    const int z = blockIdx.z;
    const float4* in;
    __half2* out;
    int n4;
    if (z == 0)      { in = x;  out = (__half2*)g_xt; n4 = ROWS * KDIM / 4; }
    else if (z == 1) { in = Wq; out = (__half2*)g_wq; n4 = KDIM * KDIM / 4; }
    else if (z == 2) { in = Wk; out = (__half2*)g_wk; n4 = KDIM * KDIM / 4; }
    else if (z == 3) { in = Wv; out = (__half2*)g_wv; n4 = KDIM * KDIM / 4; }
    else             { in = Wu; out = (__half2*)g_wu; n4 = KDIM * KDIM / 4; }
    int i = blockIdx.x * blockDim.x + threadIdx.x;
    if (i >= n4) return;
    float4 v = in[i];
    out[2 * i]     = __floats2half2_rn(v.x, v.y);
    out[2 * i + 1] = __floats2half2_rn(v.z, v.w);
}

// ---------------------------------------------------------------------------
// fp16 GEMM core: 128x128x32 CTA tile, 256 threads = 8 warps (2m x 4n),
// warp tile 64x32, 4-stage cp.async pipeline (wait_group 2, 2 iters slack),
// smem stride 40 halves (ldmatrix conflict-free).
// ---------------------------------------------------------------------------
#define GSH 40
#define GSTGH (2 * 128 * GSH)          // halves per stage (A+B)
#define GSTGB (GSTGH * 2)              // bytes per stage (20480)
#define GSMEM (4 * GSTGB)              // 81920 B

// Fused QKV projection: grid (8, 64, 3).  z selects weight/output/RoPE.
// z==0 (Q): RoPE then multiply by SOFTMAX_SCALE (pre-scaled for attention).
__global__ __launch_bounds__(256, 2) void gemm_qkv()
{
    extern __shared__ __half smh[];
    const uint32_t base_b = (uint32_t)__cvta_generic_to_shared(smh);

    const int z = blockIdx.z;
    const __half* A = g_xt;
    const __half* B = (z == 0) ? g_wq : (z == 1) ? g_wk : g_wv;
    __half* C = (z == 0) ? g_q : (z == 1) ? g_k : g_v;
    const bool do_rope = (z < 2);

    const int tid  = threadIdx.x;
    const int lane = tid & 31;
    const int warp = tid >> 5;
    const int g = lane >> 2;
    const int t = lane & 3;
    const int wm = warp >> 2;
    const int wn = warp & 3;
    const int bm = blockIdx.y * 128;
    const int bn = blockIdx.x * 128;

    float c[4][4][4];
#pragma unroll
    for (int i = 0; i < 4; i++)
#pragma unroll
        for (int j = 0; j < 4; j++)
#pragma unroll
            for (int e = 0; e < 4; e++) c[i][j][e] = 0.0f;

    const int lrow = tid >> 1;
    const int lcb  = (tid & 1) * 16;
    const __half* Ap = A + (size_t)(bm + lrow) * KDIM + lcb;
    const __half* Bp = B + (size_t)(bn + lrow) * KDIM + lcb;

    auto fill = [&](int ch, int s) {
        __half* Asd = smh + s * GSTGH + lrow * GSH + lcb;
        __half* Bsd = Asd + 128 * GSH;
        cp16(Asd, Ap + ch * 32); cp16(Asd + 8, Ap + ch * 32 + 8);
        cp16(Bsd, Bp + ch * 32); cp16(Bsd + 8, Bp + ch * 32 + 8);
    };

    fill(0, 0); CP_COMMIT();
    fill(1, 1); CP_COMMIT();
    fill(2, 2); CP_COMMIT();

    const int a_row = wm * 64 + (lane & 15);
    const int a_colh = (lane >> 4) << 3;
    const int b_row = wn * 32 + ((lane >> 4) << 3) + (lane & 7);
    const int b_colh = ((lane >> 3) & 1) << 3;

    const int NCH = KDIM / 32;           // 32
    for (int i = 0; i < NCH; i++) {
        const int s = i & 3;
        CP_WAIT2();                      // chunk i resident (2 iters slack)
        __syncthreads();
        const int j = i + 3;
        if (j < NCH) fill(j, j & 3);
        CP_COMMIT();

        const uint32_t Ab = base_b + s * GSTGB;
        const uint32_t Bb = Ab + 128 * GSH * 2;
#pragma unroll
        for (int ks = 0; ks < 2; ks++) {
            unsigned a[4][4], bf[4][2];
#pragma unroll
            for (int mt = 0; mt < 4; mt++)
                ldsm_x4(a[mt], Ab + ((a_row + mt * 16) * GSH + 16 * ks + a_colh) * 2);
#pragma unroll
            for (int ntp = 0; ntp < 2; ntp++) {
                unsigned r[4];
                ldsm_x4(r, Bb + ((b_row + ntp * 16) * GSH + 16 * ks + b_colh) * 2);
                bf[2 * ntp][0] = r[0]; bf[2 * ntp][1] = r[1];
                bf[2 * ntp + 1][0] = r[2]; bf[2 * ntp + 1][1] = r[3];
            }
#pragma unroll
            for (int mt = 0; mt < 4; mt++)
#pragma unroll
                for (int nt = 0; nt < 4; nt++)
                    mma_f16(c[mt][nt], a[mt], bf[nt]);
        }
    }

    // Epilogue: RoPE (z<2), Q also pre-scaled by SOFTMAX_SCALE; fp16 store
#pragma unroll
    for (int mt = 0; mt < 4; mt++) {
        int row = bm + wm * 64 + mt * 16 + g;
#pragma unroll
        for (int nt = 0; nt < 4; nt++) {
            int col = bn + wn * 32 + nt * 8 + 2 * t;
            float v0x = c[mt][nt][0], v0y = c[mt][nt][1];
            float v1x = c[mt][nt][2], v1y = c[mt][nt][3];
            if (do_rope) {
                int j = col >> 1;
                float theta = powf(10000.0f, -(float)j * (1.0f / (float)HALF));
                int t0 = row & (T_ - 1);
                float s0, c0; sincosf((float)t0 * theta, &s0, &c0);
                float s1, c1; sincosf((float)(t0 + 8) * theta, &s1, &c1);
                float r0x = v0x * c0 - v0y * s0;
                float r0y = v0x * s0 + v0y * c0;
                float r1x = v1x * c1 - v1y * s1;
                float r1y = v1x * s1 + v1y * c1;
                v0x = r0x; v0y = r0y; v1x = r1x; v1y = r1y;
                if (z == 0) {
                    v0x *= SOFTMAX_SCALE; v0y *= SOFTMAX_SCALE;
                    v1x *= SOFTMAX_SCALE; v1y *= SOFTMAX_SCALE;
                }
            }
            *(__half2*)&C[(size_t)row * KDIM + col] = __floats2half2_rn(v0x, v0y);
            *(__half2*)&C[(size_t)(row + 8) * KDIM + col] = __floats2half2_rn(v1x, v1y);
        }
    }
}

// Output projection: fp32 store + bias
__global__ __launch_bounds__(256, 2) void gemm_out(
    const float* __restrict__ bias, float* __restrict__ C)
{
    extern __shared__ __half smh[];
    const uint32_t base_b = (uint32_t)__cvta_generic_to_shared(smh);

    const int tid  = threadIdx.x;
    const int lane = tid & 31;
    const int warp = tid >> 5;
    const int g = lane >> 2;
    const int t = lane & 3;
    const int wm = warp >> 2;
    const int wn = warp & 3;
    const int bm = blockIdx.y * 128;
    const int bn = blockIdx.x * 128;

    float c[4][4][4];
#pragma unroll
    for (int i = 0; i < 4; i++)
#pragma unroll
        for (int j = 0; j < 4; j++)
#pragma unroll
            for (int e = 0; e < 4; e++) c[i][j][e] = 0.0f;

    const int lrow = tid >> 1;
    const int lcb  = (tid & 1) * 16;
    const __half* Ap = g_a  + (size_t)(bm + lrow) * KDIM + lcb;
    const __half* Bp = g_wu + (size_t)(bn + lrow) * KDIM + lcb;

    auto fill = [&](int ch, int s) {
        __half* Asd = smh + s * GSTGH + lrow * GSH + lcb;
        __half* Bsd = Asd + 128 * GSH;
        cp16(Asd, Ap + ch * 32); cp16(Asd + 8, Ap + ch * 32 + 8);
        cp16(Bsd, Bp + ch * 32); cp16(Bsd + 8, Bp + ch * 32 + 8);
    };

    fill(0, 0); CP_COMMIT();
    fill(1, 1); CP_COMMIT();
    fill(2, 2); CP_COMMIT();

    const int a_row = wm * 64 + (lane & 15);
    const int a_colh = (lane >> 4) << 3;
    const int b_row = wn * 32 + ((lane >> 4) << 3) + (lane & 7);
    const int b_colh = ((lane >> 3) & 1) << 3;

    const int NCH = KDIM / 32;
    for (int i = 0; i < NCH; i++) {
        const int s = i & 3;
        CP_WAIT2();
        __syncthreads();
        const int j = i + 3;
        if (j < NCH) fill(j, j & 3);
        CP_COMMIT();

        const uint32_t Ab = base_b + s * GSTGB;
        const uint32_t Bb = Ab + 128 * GSH * 2;
#pragma unroll
        for (int ks = 0; ks < 2; ks++) {
            unsigned a[4][4], bf[4][2];
#pragma unroll
            for (int mt = 0; mt < 4; mt++)
                ldsm_x4(a[mt], Ab + ((a_row + mt * 16) * GSH + 16 * ks + a_colh) * 2);
#pragma unroll
            for (int ntp = 0; ntp < 2; ntp++) {
                unsigned r[4];
                ldsm_x4(r, Bb + ((b_row + ntp * 16) * GSH + 16 * ks + b_colh) * 2);
                bf[2 * ntp][0] = r[0]; bf[2 * ntp][1] = r[1];
                bf[2 * ntp + 1][0] = r[2]; bf[2 * ntp + 1][1] = r[3];
            }
#pragma unroll
            for (int mt = 0; mt < 4; mt++)
#pragma unroll
                for (int nt = 0; nt < 4; nt++)
                    mma_f16(c[mt][nt], a[mt], bf[nt]);
        }
    }

#pragma unroll
    for (int mt = 0; mt < 4; mt++) {
        int row = bm + wm * 64 + mt * 16 + g;
#pragma unroll
        for (int nt = 0; nt < 4; nt++) {
            int col = bn + wn * 32 + nt * 8 + 2 * t;
            float bx = bias[col], by = bias[col + 1];
            *(float2*)&C[(size_t)row * KDIM + col] =
                make_float2(c[mt][nt][0] + bx, c[mt][nt][1] + by);
            *(float2*)&C[(size_t)(row + 8) * KDIM + col] =
                make_float2(c[mt][nt][2] + bx, c[mt][nt][3] + by);
        }
    }
}

// ---------------------------------------------------------------------------
// Flash attention, fp16 mma m16n8k16, 4-stage K/V cp.async pipeline.
// CTA = 128 q-rows x (batch*head), 8 warps x 16 q-rows, BN=64.
// Q fragments hoisted to registers (loaded once).  Q arrives PRE-SCALED by
// 0.125*log2e, so S is directly in log2 domain (ex2.approx softmax).
// P packed to half2 inline in softmax loop (S C-frag == PV A-frag layout).
// ---------------------------------------------------------------------------
#define QSTR 72
#define KSTR 72
#define VSTR 72
#define QSZ  (128 * QSTR)              // halves
#define SSZ  (64 * KSTR + 64 * VSTR)   // halves per K/V stage

__global__ __launch_bounds__(256, 2) void attn_f16(
    const __half* __restrict__ Q, const __half* __restrict__ K,
    const __half* __restrict__ V, __half* __restrict__ O)
{
    extern __shared__ __half smh[];
    __half* Qs = smh;
    __half* KV = smh + QSZ;            // 4 stages of [K(64xKSTR) | V(64xVSTR)]
    const uint32_t Qs_b = (uint32_t)__cvta_generic_to_shared(Qs);
    const uint32_t KV_b = (uint32_t)__cvta_generic_to_shared(KV);

    const int tid  = threadIdx.x;
    const int lane = tid & 31;
    const int warp = tid >> 5;
    const int g = lane >> 2;
    const int t = lane & 3;
    const int wrow = warp * 16;

    const int qtile = blockIdx.x;
    const int bh = blockIdx.y;
    const int b = bh >> 4;
    const int h = bh & 15;
    const size_t rowbase = (size_t)b * T_;
    const int colbase = h * HDIM;

    const int lrow4 = tid >> 2;
    const int lcb4  = (tid & 3) * 16;

    auto fill_kv = [&](int kt, int s) {
        const size_t gb = (rowbase + kt * 64 + lrow4) * KDIM + colbase + lcb4;
        __half* kd = KV + s * SSZ + lrow4 * KSTR + lcb4;
        __half* vd = kd + 64 * KSTR;
        cp16(kd, K + gb); cp16(kd + 8, K + gb + 8);
        cp16(vd, V + gb); cp16(vd + 8, V + gb + 8);
    };

    // ---- Stage Q tile [128 x 64], then K/V tiles 0..2
    {
        const int qrow = tid >> 1;
        const int qcb  = (tid & 1) * 32;
        const __half* src = Q + (rowbase + qtile * 128 + qrow) * KDIM + colbase + qcb;
        __half* dst = Qs + qrow * QSTR + qcb;
        cp16(dst, src); cp16(dst + 8, src + 8);
        cp16(dst + 16, src + 16); cp16(dst + 24, src + 24);
        CP_COMMIT();
    }
    fill_kv(0, 0); CP_COMMIT();
    fill_kv(1, 1); CP_COMMIT();
    fill_kv(2, 2); CP_COMMIT();

    // ---- Hoist Q fragments (Q group done after wait 3)
    const int qa_row = wrow + (lane & 15);
    const int qa_colh = (lane >> 4) << 3;
    unsigned qf[4][4];
    CP_WAIT3();
    __syncthreads();
#pragma unroll
    for (int ds = 0; ds < 4; ds++)
        ldsm_x4(qf[ds], Qs_b + (qa_row * QSTR + 16 * ds + qa_colh) * 2);

    float m0 = -1e30f, m1 = -1e30f, l0 = 0.0f, l1 = 0.0f;
    float o[8][4];
#pragma unroll
    for (int j = 0; j < 8; j++)
#pragma unroll
        for (int e = 0; e < 4; e++) o[j][e] = 0.0f;

    const int kb_row = ((lane >> 4) << 3) + (lane & 7);
    const int kb_colh = ((lane >> 3) & 1) << 3;
    const int vb_row = (((lane >> 3) & 1) << 3) + (lane & 7);
    const int vb_colh = (lane >> 4) << 3;

    const int NT = T_ / 64;              // 32
    for (int kt = 0; kt < NT; kt++) {
        const int s = kt & 3;
        const uint32_t Kb = KV_b + s * SSZ * 2;
        const uint32_t Vb = Kb + 64 * KSTR * 2;

        CP_WAIT2();                      // kv_kt resident (2 iters slack)
        __syncthreads();
        const int jn = kt + 3;
        if (jn < NT) fill_kv(jn, jn & 3);
        CP_COMMIT();

        // ---- S = Q K^T (warp tile 16 x 64), S already in log2 domain
        float sc[8][4];
#pragma unroll
        for (int j = 0; j < 8; j++)
#pragma unroll
            for (int e = 0; e < 4; e++) sc[j][e] = 0.0f;

#pragma unroll
        for (int ds = 0; ds < 4; ds++) {
#pragma unroll
            for (int jj = 0; jj < 4; jj++) {
                unsigned r[4];
                ldsm_x4(r, Kb + ((16 * jj + kb_row) * KSTR + 16 * ds + kb_colh) * 2);
                mma_f16(sc[2 * jj], qf[ds], r);
                mma_f16(sc[2 * jj + 1], qf[ds], r + 2);
            }
        }

        // ---- Online softmax (rows g, g+8), exp via ex2; pack P inline
        float mx0 = -1e30f, mx1 = -1e30f;
#pragma unroll
        for (int j = 0; j < 8; j++) {
            mx0 = fmaxf(mx0, fmaxf(sc[j][0], sc[j][1]));
            mx1 = fmaxf(mx1, fmaxf(sc[j][2], sc[j][3]));
        }
        mx0 = fmaxf(mx0, __shfl_xor_sync(0xffffffffu, mx0, 1));
        mx0 = fmaxf(mx0, __shfl_xor_sync(0xffffffffu, mx0, 2));
        mx1 = fmaxf(mx1, __shfl_xor_sync(0xffffffffu, mx1, 1));
        mx1 = fmaxf(mx1, __shfl_xor_sync(0xffffffffu, mx1, 2));

        float mn0 = fmaxf(m0, mx0);
        float mn1 = fmaxf(m1, mx1);
        float corr0 = ex2f(m0 - mn0);
        float corr1 = ex2f(m1 - mn1);

        unsigned pf[4][4];
        float rs0 = 0.0f, rs1 = 0.0f;
#pragma unroll
        for (int j = 0; j < 8; j++) {
            __half2 h01 = __floats2half2_rn(ex2f(sc[j][0] - mn0), ex2f(sc[j][1] - mn0));
            __half2 h23 = __floats2half2_rn(ex2f(sc[j][2] - mn1), ex2f(sc[j][3] - mn1));
            float2 f01 = __half22float2(h01);   // rounded values for l-sum
            float2 f23 = __half22float2(h23);
            rs0 += f01.x + f01.y;
            rs1 += f23.x + f23.y;
            pf[j >> 1][((j & 1) << 1) + 0] = *(unsigned*)&h01;
            pf[j >> 1][((j & 1) << 1) + 1] = *(unsigned*)&h23;
        }
        rs0 += __shfl_xor_sync(0xffffffffu, rs0, 1);
        rs0 += __shfl_xor_sync(0xffffffffu, rs0, 2);
        rs1 += __shfl_xor_sync(0xffffffffu, rs1, 1);
        rs1 += __shfl_xor_sync(0xffffffffu, rs1, 2);

        l0 = l0 * corr0 + rs0;
        l1 = l1 * corr1 + rs1;
#pragma unroll
        for (int j = 0; j < 8; j++) {
            o[j][0] *= corr0; o[j][1] *= corr0;
            o[j][2] *= corr1; o[j][3] *= corr1;
        }
        m0 = mn0; m1 = mn1;

        // ---- O += P V (V via ldmatrix.trans)
#pragma unroll
        for (int s2 = 0; s2 < 4; s2++) {
#pragma unroll
            for (int jj2 = 0; jj2 < 4; jj2++) {
                unsigned r[4];
                ldsm_x4_t(r, Vb + ((16 * s2 + vb_row) * VSTR + 16 * jj2 + vb_colh) * 2);
                mma_f16(o[2 * jj2], pf[s2], r);
                mma_f16(o[2 * jj2 + 1], pf[s2], r + 2);
            }
        }
    }

    // ---- Normalize, store fp16 ([b*t][h*64])
    float inv0 = 1.0f / l0;
    float inv1 = 1.0f / l1;
    size_t orow0 = (rowbase + qtile * 128 + wrow + g) * KDIM + colbase;
    size_t orow1 = orow0 + (size_t)8 * KDIM;
#pragma unroll
    for (int j = 0; j < 8; j++) {
        int col = 8 * j + 2 * t;
        *(__half2*)&O[orow0 + col] = __floats2half2_rn(o[j][0] * inv0, o[j][1] * inv0);
        *(__half2*)&O[orow1 + col] = __floats2half2_rn(o[j][2] * inv1, o[j][3] * inv1);
    }
}

// ---------------------------------------------------------------------------
// Launcher
// ---------------------------------------------------------------------------
extern "C" void kernel_launch(void* const* d_in, const int* in_sizes, int n_in,
                              void* d_out, int out_size)
{
    const float* x  = (const float*)d_in[0];
    const float* Wq = (const float*)d_in[1];
    const float* Wk = (const float*)d_in[2];
    const float* Wv = (const float*)d_in[3];
    const float* Wu = (const float*)d_in[4];
    const float* bu = (const float*)d_in[5];
    float* out = (float*)d_out;

    __half *q, *k, *v, *a;
    cudaGetSymbolAddress((void**)&q, g_q);
    cudaGetSymbolAddress((void**)&k, g_k);
    cudaGetSymbolAddress((void**)&v, g_v);
    cudaGetSymbolAddress((void**)&a, g_a);

    // Pre-pass: one launch rounds x + all 4 weights to fp16
    {
        int blocks_x = (ROWS * KDIM / 4 + 255) / 256;   // 8192
        round_all<<<dim3(blocks_x, 1, 5), 256>>>(
            (const float4*)x, (const float4*)Wq, (const float4*)Wk,
            (const float4*)Wv, (const float4*)Wu);
    }

    cudaFuncSetAttribute(gemm_qkv, cudaFuncAttributeMaxDynamicSharedMemorySize, GSMEM);
    cudaFuncSetAttribute(gemm_out, cudaFuncAttributeMaxDynamicSharedMemorySize, GSMEM);

    // Fused QKV projections (one launch, grid.z selects Q/K/V)
    gemm_qkv<<<dim3(KDIM / 128, ROWS / 128, 3), 256, GSMEM>>>();

    // Attention
    const int attn_smem = (QSZ + 4 * SSZ) * (int)sizeof(__half);  // 92160 B
    cudaFuncSetAttribute(attn_f16, cudaFuncAttributeMaxDynamicSharedMemorySize, attn_smem);
    attn_f16<<<dim3(T_ / 128, B_ * HEADS), 256, attn_smem>>>(q, k, v, a);

    // Output projection + bias (fp32 store)
    gemm_out<<<dim3(KDIM / 128, ROWS / 128), 256, GSMEM>>>(bu, out);
}

// round 12
// speedup vs baseline: 3.1400x; 1.0237x over previous
#include <cuda_runtime.h>
#include <cuda_fp16.h>
#include <math.h>
#include <cstdint>

// Problem constants
#define B_      4
#define T_      2048
#define KDIM    1024
#define HEADS   16
#define HDIM    64
#define ROWS    (B_ * T_)          // 8192
#define HALF    (KDIM / 2)         // 512

// ---------------------------------------------------------------------------
// Scratch (device globals: allocation-free per harness rules)
// ---------------------------------------------------------------------------
__device__ __align__(16) __half g_q[ROWS * KDIM];
__device__ __align__(16) __half g_k[ROWS * KDIM];
__device__ __align__(16) __half g_v[ROWS * KDIM];
__device__ __align__(16) __half g_a[ROWS * KDIM];
__device__ __align__(16) __half g_xt[ROWS * KDIM];
__device__ __align__(16) __half g_wq[KDIM * KDIM];
__device__ __align__(16) __half g_wk[KDIM * KDIM];
__device__ __align__(16) __half g_wv[KDIM * KDIM];
__device__ __align__(16) __half g_wu[KDIM * KDIM];

// ---------------------------------------------------------------------------
// Helpers
// ---------------------------------------------------------------------------
__device__ __forceinline__ void mma_f16(float* c, const unsigned* a, const unsigned* b) {
    asm volatile(
        "mma.sync.aligned.m16n8k16.row.col.f32.f16.f16.f32 "
        "{%0,%1,%2,%3}, {%4,%5,%6,%7}, {%8,%9}, {%0,%1,%2,%3};\n"
        : "+f"(c[0]), "+f"(c[1]), "+f"(c[2]), "+f"(c[3])
        : "r"(a[0]), "r"(a[1]), "r"(a[2]), "r"(a[3]), "r"(b[0]), "r"(b[1]));
}

__device__ __forceinline__ void ldsm_x4(unsigned* r, uint32_t addr) {
    asm volatile("ldmatrix.sync.aligned.m8n8.x4.shared.b16 {%0,%1,%2,%3}, [%4];"
        : "=r"(r[0]), "=r"(r[1]), "=r"(r[2]), "=r"(r[3]) : "r"(addr));
}
__device__ __forceinline__ void ldsm_x4_t(unsigned* r, uint32_t addr) {
    asm volatile("ldmatrix.sync.aligned.m8n8.x4.trans.shared.b16 {%0,%1,%2,%3}, [%4];"
        : "=r"(r[0]), "=r"(r[1]), "=r"(r[2]), "=r"(r[3]) : "r"(addr));
}

__device__ __forceinline__ void cp16(void* dst_smem, const void* src) {
    unsigned d = (unsigned)__cvta_generic_to_shared(dst_smem);
    asm volatile("cp.async.cg.shared.global [%0], [%1], 16;\n" :: "r"(d), "l"(src));
}
#define CP_COMMIT() asm volatile("cp.async.commit_group;\n" ::: "memory")
#define CP_WAIT2()  asm volatile("cp.async.wait_group 2;\n" ::: "memory")
#define CP_WAIT3()  asm volatile("cp.async.wait_group 3;\n" ::: "memory")

__device__ __forceinline__ float ex2f(float x) {
    float y;
    asm("ex2.approx.f32 %0, %1;" : "=f"(y) : "f"(x));
    return y;
}
// packed half2 exp2 (MUFU, 2 values per op)
__device__ __forceinline__ unsigned h2ex2(__half2 x) {
    unsigned y;
    asm("ex2.approx.f16x2 %0, %1;" : "=r"(y) : "r"(*(unsigned*)&x));
    return y;
}

#define SOFTMAX_SCALE 0.1803368801111244f   // 0.125 * log2(e)

// ---------------------------------------------------------------------------
// Pre-pass (single launch): z=0 rounds x, z=1..4 round the four weights
// ---------------------------------------------------------------------------
__global__ void round_all(const float4* __restrict__ x,
                          const float4* __restrict__ Wq,
                          const float4* __restrict__ Wk,
                          const float4* __restrict__ Wv,
                          const float4* __restrict__ Wu)
{
    const int z = blockIdx.z;
    const float4* in;
    __half2* out;
    int n4;
    if (z == 0)      { in = x;  out = (__half2*)g_xt; n4 = ROWS * KDIM / 4; }
    else if (z == 1) { in = Wq; out = (__half2*)g_wq; n4 = KDIM * KDIM / 4; }
    else if (z == 2) { in = Wk; out = (__half2*)g_wk; n4 = KDIM * KDIM / 4; }
    else if (z == 3) { in = Wv; out = (__half2*)g_wv; n4 = KDIM * KDIM / 4; }
    else             { in = Wu; out = (__half2*)g_wu; n4 = KDIM * KDIM / 4; }
    int i = blockIdx.x * blockDim.x + threadIdx.x;
    if (i >= n4) return;
    float4 v = in[i];
    out[2 * i]     = __floats2half2_rn(v.x, v.y);
    out[2 * i + 1] = __floats2half2_rn(v.z, v.w);
}

// ---------------------------------------------------------------------------
// fp16 GEMM core: 128x128x32 CTA tile, 256 threads = 8 warps (2m x 4n),
// warp tile 64x32, 4-stage cp.async pipeline (wait_group 2),
// smem stride 40 halves (ldmatrix conflict-free).
// ---------------------------------------------------------------------------
#define GSH 40
#define GSTGH (2 * 128 * GSH)          // halves per stage (A+B)
#define GSTGB (GSTGH * 2)              // bytes per stage (20480)
#define GSMEM (4 * GSTGB)              // 81920 B

// Fused QKV projection: grid (8, 64, 3).  z selects weight/output/RoPE.
// z==0 (Q): RoPE then multiply by SOFTMAX_SCALE (pre-scaled for attention).
__global__ __launch_bounds__(256, 2) void gemm_qkv()
{
    extern __shared__ __half smh[];
    const uint32_t base_b = (uint32_t)__cvta_generic_to_shared(smh);

    const int z = blockIdx.z;
    const __half* A = g_xt;
    const __half* B = (z == 0) ? g_wq : (z == 1) ? g_wk : g_wv;
    __half* C = (z == 0) ? g_q : (z == 1) ? g_k : g_v;
    const bool do_rope = (z < 2);

    const int tid  = threadIdx.x;
    const int lane = tid & 31;
    const int warp = tid >> 5;
    const int g = lane >> 2;
    const int t = lane & 3;
    const int wm = warp >> 2;
    const int wn = warp & 3;
    const int bm = blockIdx.y * 128;
    const int bn = blockIdx.x * 128;

    float c[4][4][4];
#pragma unroll
    for (int i = 0; i < 4; i++)
#pragma unroll
        for (int j = 0; j < 4; j++)
#pragma unroll
            for (int e = 0; e < 4; e++) c[i][j][e] = 0.0f;

    const int lrow = tid >> 1;
    const int lcb  = (tid & 1) * 16;
    const __half* Ap = A + (size_t)(bm + lrow) * KDIM + lcb;
    const __half* Bp = B + (size_t)(bn + lrow) * KDIM + lcb;

    auto fill = [&](int ch, int s) {
        __half* Asd = smh + s * GSTGH + lrow * GSH + lcb;
        __half* Bsd = Asd + 128 * GSH;
        cp16(Asd, Ap + ch * 32); cp16(Asd + 8, Ap + ch * 32 + 8);
        cp16(Bsd, Bp + ch * 32); cp16(Bsd + 8, Bp + ch * 32 + 8);
    };

    fill(0, 0); CP_COMMIT();
    fill(1, 1); CP_COMMIT();
    fill(2, 2); CP_COMMIT();

    const int a_row = wm * 64 + (lane & 15);
    const int a_colh = (lane >> 4) << 3;
    const int b_row = wn * 32 + ((lane >> 4) << 3) + (lane & 7);
    const int b_colh = ((lane >> 3) & 1) << 3;

    const int NCH = KDIM / 32;           // 32
    for (int i = 0; i < NCH; i++) {
        const int s = i & 3;
        CP_WAIT2();
        __syncthreads();
        const int j = i + 3;
        if (j < NCH) fill(j, j & 3);
        CP_COMMIT();

        const uint32_t Ab = base_b + s * GSTGB;
        const uint32_t Bb = Ab + 128 * GSH * 2;
#pragma unroll
        for (int ks = 0; ks < 2; ks++) {
            unsigned a[4][4], bf[4][2];
#pragma unroll
            for (int mt = 0; mt < 4; mt++)
                ldsm_x4(a[mt], Ab + ((a_row + mt * 16) * GSH + 16 * ks + a_colh) * 2);
#pragma unroll
            for (int ntp = 0; ntp < 2; ntp++) {
                unsigned r[4];
                ldsm_x4(r, Bb + ((b_row + ntp * 16) * GSH + 16 * ks + b_colh) * 2);
                bf[2 * ntp][0] = r[0]; bf[2 * ntp][1] = r[1];
                bf[2 * ntp + 1][0] = r[2]; bf[2 * ntp + 1][1] = r[3];
            }
#pragma unroll
            for (int mt = 0; mt < 4; mt++)
#pragma unroll
                for (int nt = 0; nt < 4; nt++)
                    mma_f16(c[mt][nt], a[mt], bf[nt]);
        }
    }

    // Epilogue: RoPE (z<2), Q also pre-scaled by SOFTMAX_SCALE; fp16 store
#pragma unroll
    for (int mt = 0; mt < 4; mt++) {
        int row = bm + wm * 64 + mt * 16 + g;
#pragma unroll
        for (int nt = 0; nt < 4; nt++) {
            int col = bn + wn * 32 + nt * 8 + 2 * t;
            float v0x = c[mt][nt][0], v0y = c[mt][nt][1];
            float v1x = c[mt][nt][2], v1y = c[mt][nt][3];
            if (do_rope) {
                int j = col >> 1;
                float theta = powf(10000.0f, -(float)j * (1.0f / (float)HALF));
                int t0 = row & (T_ - 1);
                float s0, c0; sincosf((float)t0 * theta, &s0, &c0);
                float s1, c1; sincosf((float)(t0 + 8) * theta, &s1, &c1);
                float r0x = v0x * c0 - v0y * s0;
                float r0y = v0x * s0 + v0y * c0;
                float r1x = v1x * c1 - v1y * s1;
                float r1y = v1x * s1 + v1y * c1;
                v0x = r0x; v0y = r0y; v1x = r1x; v1y = r1y;
                if (z == 0) {
                    v0x *= SOFTMAX_SCALE; v0y *= SOFTMAX_SCALE;
                    v1x *= SOFTMAX_SCALE; v1y *= SOFTMAX_SCALE;
                }
            }
            *(__half2*)&C[(size_t)row * KDIM + col] = __floats2half2_rn(v0x, v0y);
            *(__half2*)&C[(size_t)(row + 8) * KDIM + col] = __floats2half2_rn(v1x, v1y);
        }
    }
}

// Output projection: fp32 store + bias
__global__ __launch_bounds__(256, 2) void gemm_out(
    const float* __restrict__ bias, float* __restrict__ C)
{
    extern __shared__ __half smh[];
    const uint32_t base_b = (uint32_t)__cvta_generic_to_shared(smh);

    const int tid  = threadIdx.x;
    const int lane = tid & 31;
    const int warp = tid >> 5;
    const int g = lane >> 2;
    const int t = lane & 3;
    const int wm = warp >> 2;
    const int wn = warp & 3;
    const int bm = blockIdx.y * 128;
    const int bn = blockIdx.x * 128;

    float c[4][4][4];
#pragma unroll
    for (int i = 0; i < 4; i++)
#pragma unroll
        for (int j = 0; j < 4; j++)
#pragma unroll
            for (int e = 0; e < 4; e++) c[i][j][e] = 0.0f;

    const int lrow = tid >> 1;
    const int lcb  = (tid & 1) * 16;
    const __half* Ap = g_a  + (size_t)(bm + lrow) * KDIM + lcb;
    const __half* Bp = g_wu + (size_t)(bn + lrow) * KDIM + lcb;

    auto fill = [&](int ch, int s) {
        __half* Asd = smh + s * GSTGH + lrow * GSH + lcb;
        __half* Bsd = Asd + 128 * GSH;
        cp16(Asd, Ap + ch * 32); cp16(Asd + 8, Ap + ch * 32 + 8);
        cp16(Bsd, Bp + ch * 32); cp16(Bsd + 8, Bp + ch * 32 + 8);
    };

    fill(0, 0); CP_COMMIT();
    fill(1, 1); CP_COMMIT();
    fill(2, 2); CP_COMMIT();

    const int a_row = wm * 64 + (lane & 15);
    const int a_colh = (lane >> 4) << 3;
    const int b_row = wn * 32 + ((lane >> 4) << 3) + (lane & 7);
    const int b_colh = ((lane >> 3) & 1) << 3;

    const int NCH = KDIM / 32;
    for (int i = 0; i < NCH; i++) {
        const int s = i & 3;
        CP_WAIT2();
        __syncthreads();
        const int j = i + 3;
        if (j < NCH) fill(j, j & 3);
        CP_COMMIT();

        const uint32_t Ab = base_b + s * GSTGB;
        const uint32_t Bb = Ab + 128 * GSH * 2;
#pragma unroll
        for (int ks = 0; ks < 2; ks++) {
            unsigned a[4][4], bf[4][2];
#pragma unroll
            for (int mt = 0; mt < 4; mt++)
                ldsm_x4(a[mt], Ab + ((a_row + mt * 16) * GSH + 16 * ks + a_colh) * 2);
#pragma unroll
            for (int ntp = 0; ntp < 2; ntp++) {
                unsigned r[4];
                ldsm_x4(r, Bb + ((b_row + ntp * 16) * GSH + 16 * ks + b_colh) * 2);
                bf[2 * ntp][0] = r[0]; bf[2 * ntp][1] = r[1];
                bf[2 * ntp + 1][0] = r[2]; bf[2 * ntp + 1][1] = r[3];
            }
#pragma unroll
            for (int mt = 0; mt < 4; mt++)
#pragma unroll
                for (int nt = 0; nt < 4; nt++)
                    mma_f16(c[mt][nt], a[mt], bf[nt]);
        }
    }

#pragma unroll
    for (int mt = 0; mt < 4; mt++) {
        int row = bm + wm * 64 + mt * 16 + g;
#pragma unroll
        for (int nt = 0; nt < 4; nt++) {
            int col = bn + wn * 32 + nt * 8 + 2 * t;
            float bx = bias[col], by = bias[col + 1];
            *(float2*)&C[(size_t)row * KDIM + col] =
                make_float2(c[mt][nt][0] + bx, c[mt][nt][1] + by);
            *(float2*)&C[(size_t)(row + 8) * KDIM + col] =
                make_float2(c[mt][nt][2] + bx, c[mt][nt][3] + by);
        }
    }
}

// ---------------------------------------------------------------------------
// Flash attention, fp16 mma m16n8k16, 4-stage K/V cp.async pipeline.
// CTA = 128 q-rows x (batch*head), 8 warps x 16 q-rows, BN=64.
// Q fragments hoisted; Q PRE-SCALED by 0.125*log2e (S in log2 domain).
// exp via ex2.approx.f16x2 (2 values / MUFU op, output IS the P fragment).
// Warp-uniform corr-skip: when no row max changed, the rescale (corr==1.0
// exactly) is skipped with bit-identical results.
// ---------------------------------------------------------------------------
#define QSTR 72
#define KSTR 72
#define VSTR 72
#define QSZ  (128 * QSTR)              // halves
#define SSZ  (64 * KSTR + 64 * VSTR)   // halves per K/V stage

__global__ __launch_bounds__(256, 2) void attn_f16(
    const __half* __restrict__ Q, const __half* __restrict__ K,
    const __half* __restrict__ V, __half* __restrict__ O)
{
    extern __shared__ __half smh[];
    __half* Qs = smh;
    __half* KV = smh + QSZ;            // 4 stages of [K(64xKSTR) | V(64xVSTR)]
    const uint32_t Qs_b = (uint32_t)__cvta_generic_to_shared(Qs);
    const uint32_t KV_b = (uint32_t)__cvta_generic_to_shared(KV);

    const int tid  = threadIdx.x;
    const int lane = tid & 31;
    const int warp = tid >> 5;
    const int g = lane >> 2;
    const int t = lane & 3;
    const int wrow = warp * 16;

    const int qtile = blockIdx.x;
    const int bh = blockIdx.y;
    const int b = bh >> 4;
    const int h = bh & 15;
    const size_t rowbase = (size_t)b * T_;
    const int colbase = h * HDIM;

    const int lrow4 = tid >> 2;
    const int lcb4  = (tid & 3) * 16;

    auto fill_kv = [&](int kt, int s) {
        const size_t gb = (rowbase + kt * 64 + lrow4) * KDIM + colbase + lcb4;
        __half* kd = KV + s * SSZ + lrow4 * KSTR + lcb4;
        __half* vd = kd + 64 * KSTR;
        cp16(kd, K + gb); cp16(kd + 8, K + gb + 8);
        cp16(vd, V + gb); cp16(vd + 8, V + gb + 8);
    };

    // ---- Stage Q tile [128 x 64], then K/V tiles 0..2
    {
        const int qrow = tid >> 1;
        const int qcb  = (tid & 1) * 32;
        const __half* src = Q + (rowbase + qtile * 128 + qrow) * KDIM + colbase + qcb;
        __half* dst = Qs + qrow * QSTR + qcb;
        cp16(dst, src); cp16(dst + 8, src + 8);
        cp16(dst + 16, src + 16); cp16(dst + 24, src + 24);
        CP_COMMIT();
    }
    fill_kv(0, 0); CP_COMMIT();
    fill_kv(1, 1); CP_COMMIT();
    fill_kv(2, 2); CP_COMMIT();

    // ---- Hoist Q fragments (Q group done after wait 3)
    const int qa_row = wrow + (lane & 15);
    const int qa_colh = (lane >> 4) << 3;
    unsigned qf[4][4];
    CP_WAIT3();
    __syncthreads();
#pragma unroll
    for (int ds = 0; ds < 4; ds++)
        ldsm_x4(qf[ds], Qs_b + (qa_row * QSTR + 16 * ds + qa_colh) * 2);

    float m0 = -1e30f, m1 = -1e30f, l0 = 0.0f, l1 = 0.0f;
    float o[8][4];
#pragma unroll
    for (int j = 0; j < 8; j++)
#pragma unroll
        for (int e = 0; e < 4; e++) o[j][e] = 0.0f;

    const int kb_row = ((lane >> 4) << 3) + (lane & 7);
    const int kb_colh = ((lane >> 3) & 1) << 3;
    const int vb_row = (((lane >> 3) & 1) << 3) + (lane & 7);
    const int vb_colh = (lane >> 4) << 3;

    const int NT = T_ / 64;              // 32
    for (int kt = 0; kt < NT; kt++) {
        const int s = kt & 3;
        const uint32_t Kb = KV_b + s * SSZ * 2;
        const uint32_t Vb = Kb + 64 * KSTR * 2;

        CP_WAIT2();
        __syncthreads();
        const int jn = kt + 3;
        if (jn < NT) fill_kv(jn, jn & 3);
        CP_COMMIT();

        // ---- S = Q K^T (warp tile 16 x 64), S already in log2 domain
        float sc[8][4];
#pragma unroll
        for (int j = 0; j < 8; j++)
#pragma unroll
            for (int e = 0; e < 4; e++) sc[j][e] = 0.0f;

#pragma unroll
        for (int ds = 0; ds < 4; ds++) {
#pragma unroll
            for (int jj = 0; jj < 4; jj++) {
                unsigned r[4];
                ldsm_x4(r, Kb + ((16 * jj + kb_row) * KSTR + 16 * ds + kb_colh) * 2);
                mma_f16(sc[2 * jj], qf[ds], r);
                mma_f16(sc[2 * jj + 1], qf[ds], r + 2);
            }
        }

        // ---- Online softmax (rows g, g+8)
        float mx0 = -1e30f, mx1 = -1e30f;
#pragma unroll
        for (int j = 0; j < 8; j++) {
            mx0 = fmaxf(mx0, fmaxf(sc[j][0], sc[j][1]));
            mx1 = fmaxf(mx1, fmaxf(sc[j][2], sc[j][3]));
        }
        mx0 = fmaxf(mx0, __shfl_xor_sync(0xffffffffu, mx0, 1));
        mx0 = fmaxf(mx0, __shfl_xor_sync(0xffffffffu, mx0, 2));
        mx1 = fmaxf(mx1, __shfl_xor_sync(0xffffffffu, mx1, 1));
        mx1 = fmaxf(mx1, __shfl_xor_sync(0xffffffffu, mx1, 2));

        float mn0 = fmaxf(m0, mx0);
        float mn1 = fmaxf(m1, mx1);

        // P = exp2(S - m) via packed f16x2 MUFU; output is the mma fragment.
        unsigned pf[4][4];
        float rs0 = 0.0f, rs1 = 0.0f;
#pragma unroll
        for (int j = 0; j < 8; j++) {
            unsigned h01 = h2ex2(__floats2half2_rn(sc[j][0] - mn0, sc[j][1] - mn0));
            unsigned h23 = h2ex2(__floats2half2_rn(sc[j][2] - mn1, sc[j][3] - mn1));
            float2 f01 = __half22float2(*(__half2*)&h01);   // rounded values for l-sum
            float2 f23 = __half22float2(*(__half2*)&h23);
            rs0 += f01.x + f01.y;
            rs1 += f23.x + f23.y;
            pf[j >> 1][((j & 1) << 1) + 0] = h01;
            pf[j >> 1][((j & 1) << 1) + 1] = h23;
        }
        rs0 += __shfl_xor_sync(0xffffffffu, rs0, 1);
        rs0 += __shfl_xor_sync(0xffffffffu, rs0, 2);
        rs1 += __shfl_xor_sync(0xffffffffu, rs1, 1);
        rs1 += __shfl_xor_sync(0xffffffffu, rs1, 2);

        // Warp-uniform corr-skip: corr==1.0 exactly when max unchanged.
        bool nochange = (mn0 == m0) && (mn1 == m1);
        if (__all_sync(0xffffffffu, nochange)) {
            l0 += rs0;
            l1 += rs1;
        } else {
            float corr0 = ex2f(m0 - mn0);
            float corr1 = ex2f(m1 - mn1);
            l0 = l0 * corr0 + rs0;
            l1 = l1 * corr1 + rs1;
#pragma unroll
            for (int j = 0; j < 8; j++) {
                o[j][0] *= corr0; o[j][1] *= corr0;
                o[j][2] *= corr1; o[j][3] *= corr1;
            }
            m0 = mn0; m1 = mn1;
        }

        // ---- O += P V (V via ldmatrix.trans)
#pragma unroll
        for (int s2 = 0; s2 < 4; s2++) {
#pragma unroll
            for (int jj2 = 0; jj2 < 4; jj2++) {
                unsigned r[4];
                ldsm_x4_t(r, Vb + ((16 * s2 + vb_row) * VSTR + 16 * jj2 + vb_colh) * 2);
                mma_f16(o[2 * jj2], pf[s2], r);
                mma_f16(o[2 * jj2 + 1], pf[s2], r + 2);
            }
        }
    }

    // ---- Normalize, store fp16 ([b*t][h*64])
    float inv0 = 1.0f / l0;
    float inv1 = 1.0f / l1;
    size_t orow0 = (rowbase + qtile * 128 + wrow + g) * KDIM + colbase;
    size_t orow1 = orow0 + (size_t)8 * KDIM;
#pragma unroll
    for (int j = 0; j < 8; j++) {
        int col = 8 * j + 2 * t;
        *(__half2*)&O[orow0 + col] = __floats2half2_rn(o[j][0] * inv0, o[j][1] * inv0);
        *(__half2*)&O[orow1 + col] = __floats2half2_rn(o[j][2] * inv1, o[j][3] * inv1);
    }
}

// ---------------------------------------------------------------------------
// Launcher
// ---------------------------------------------------------------------------
extern "C" void kernel_launch(void* const* d_in, const int* in_sizes, int n_in,
                              void* d_out, int out_size)
{
    const float* x  = (const float*)d_in[0];
    const float* Wq = (const float*)d_in[1];
    const float* Wk = (const float*)d_in[2];
    const float* Wv = (const float*)d_in[3];
    const float* Wu = (const float*)d_in[4];
    const float* bu = (const float*)d_in[5];
    float* out = (float*)d_out;

    __half *q, *k, *v, *a;
    cudaGetSymbolAddress((void**)&q, g_q);
    cudaGetSymbolAddress((void**)&k, g_k);
    cudaGetSymbolAddress((void**)&v, g_v);
    cudaGetSymbolAddress((void**)&a, g_a);

    // Pre-pass: one launch rounds x + all 4 weights to fp16
    {
        int blocks_x = (ROWS * KDIM / 4 + 255) / 256;   // 8192
        round_all<<<dim3(blocks_x, 1, 5), 256>>>(
            (const float4*)x, (const float4*)Wq, (const float4*)Wk,
            (const float4*)Wv, (const float4*)Wu);
    }

    cudaFuncSetAttribute(gemm_qkv, cudaFuncAttributeMaxDynamicSharedMemorySize, GSMEM);
    cudaFuncSetAttribute(gemm_out, cudaFuncAttributeMaxDynamicSharedMemorySize, GSMEM);

    // Fused QKV projections (one launch, grid.z selects Q/K/V)
    gemm_qkv<<<dim3(KDIM / 128, ROWS / 128, 3), 256, GSMEM>>>();

    // Attention
    const int attn_smem = (QSZ + 4 * SSZ) * (int)sizeof(__half);  // 92160 B
    cudaFuncSetAttribute(attn_f16, cudaFuncAttributeMaxDynamicSharedMemorySize, attn_smem);
    attn_f16<<<dim3(T_ / 128, B_ * HEADS), 256, attn_smem>>>(q, k, v, a);

    // Output projection + bias (fp32 store)
    gemm_out<<<dim3(KDIM / 128, ROWS / 128), 256, GSMEM>>>(bu, out);
}